// round 14
// baseline (speedup 1.0000x reference)
#include <cuda_runtime.h>
#include <cuda_bf16.h>
#include <math.h>
#include <stdint.h>

#define BB 256
#define SS 512
#define RR 128
#define HH 512
#define TT 96
#define GG 2048   // 4*H
#define K2 1024   // 2*H

// ---------------- device scratch ----------------
__device__ __nv_bfloat16 g_hsb[(size_t)SS * BB * HH];   // encoder hidden states bf16 [s][b][h]
__device__ float g_hbuf[2][BB * HH];                    // ping-pong hidden fp32 (for out proj)
__device__ float g_c[BB * HH];                          // cell state fp32 (decoder)
__device__ __nv_bfloat16 g_hhi[2][BB * HH];             // bf16 h ping-pong (hi only)
__device__ __nv_bfloat16 g_ctxhi[BB * HH];              // bf16 context (hi only)
__device__ __nv_bfloat16 g_Wenc_hi[GG * HH],  g_Wenc_lo[GG * HH];
__device__ __nv_bfloat16 g_WA_hi[(GG + HH) * HH], g_WA_lo[(GG + HH) * HH]; // [gates_h | At]
__device__ __nv_bfloat16 g_Wc_hi[GG * HH], g_Wc_lo[GG * HH];               // ctx half of dec Wih
__device__ float g_gates[BB * GG];                     // cached gates_h (fp32)
__device__ float g_q2p[4][BB * HH];                    // q2 split-K partials (4-way)
__device__ float g_v2[GG], g_u2[GG], g_bd2[GG];
__device__ float g_WkT[HH * HH], g_WqT[HH * HH];
__device__ float g_bqk[HH];
__device__ float g_encT[SS * BB];                      // enc_inputs transposed [s][b]

// ---- encoder per-m-group barriers (4 groups x 32 CTAs) ----
__device__ unsigned g_mbar_count[4] = {0, 0, 0, 0};
__device__ volatile unsigned g_mbar_gen[4] = {0, 0, 0, 0};

// ---- decoder 2-level tree barrier (8 groups x 16 CTAs -> root of 8) ----
__device__ unsigned g_gcount[8] = {0, 0, 0, 0, 0, 0, 0, 0};
__device__ unsigned g_rcount = 0;
__device__ volatile unsigned g_ggen = 0;

// ---------------- helpers ----------------
__device__ __forceinline__ uint32_t smem_u32(const void* p) {
    uint32_t a;
    asm("{ .reg .u64 t; cvta.to.shared.u64 t, %1; cvt.u32.u64 %0, t; }" : "=r"(a) : "l"(p));
    return a;
}
__device__ __forceinline__ void cp16(uint32_t dst, const void* src) {
    asm volatile("cp.async.cg.shared.global [%0], [%1], 16;" :: "r"(dst), "l"(src) : "memory");
}
#define CP_COMMIT() asm volatile("cp.async.commit_group;" ::: "memory")
#define CP_WAIT2()  asm volatile("cp.async.wait_group 2;" ::: "memory")
#define CP_WAIT0()  asm volatile("cp.async.wait_group 0;" ::: "memory")

__device__ __forceinline__ void ldm4(uint32_t* r, uint32_t addr) {
    asm volatile("ldmatrix.sync.aligned.m8n8.x4.shared.b16 {%0,%1,%2,%3}, [%4];"
                 : "=r"(r[0]), "=r"(r[1]), "=r"(r[2]), "=r"(r[3]) : "r"(addr));
}
__device__ __forceinline__ void mma16816(float* c, const uint32_t* a, uint32_t b0, uint32_t b1) {
    asm volatile(
        "mma.sync.aligned.m16n8k16.row.col.f32.bf16.bf16.f32 "
        "{%0,%1,%2,%3}, {%4,%5,%6,%7}, {%8,%9}, {%0,%1,%2,%3};"
        : "+f"(c[0]), "+f"(c[1]), "+f"(c[2]), "+f"(c[3])
        : "r"(a[0]), "r"(a[1]), "r"(a[2]), "r"(a[3]), "r"(b0), "r"(b1));
}

// fast sigmoid/tanh (~2ulp via __expf)
__device__ __forceinline__ float fsig(float x) {
    return __fdividef(1.f, 1.f + __expf(-x));
}
__device__ __forceinline__ float ftanh(float x) {
    float e = __expf(2.f * x);
    return 1.f - __fdividef(2.f, e + 1.f);
}

// encoder: per-m-group barrier (32 CTAs sharing blockIdx.y)
__device__ __forceinline__ void msync(int grp) {
    __syncthreads();
    if (threadIdx.x == 0) {
        __threadfence();
        unsigned gen = g_mbar_gen[grp];
        unsigned t = atomicInc(&g_mbar_count[grp], 31);
        if (t == 31) {
            g_mbar_gen[grp] = gen + 1;
        } else {
            while (g_mbar_gen[grp] == gen) { }
        }
        __threadfence();
    }
    __syncthreads();
}

// decoder: 2-level tree barrier across 128 CTAs
__device__ __forceinline__ void grid_sync2(int cta) {
    __syncthreads();
    if (threadIdx.x == 0) {
        __threadfence();
        unsigned gen = g_ggen;
        unsigned t = atomicInc(&g_gcount[cta >> 4], 15);
        if (t == 15) {
            unsigned r = atomicInc(&g_rcount, 7);
            if (r == 7) {
                g_ggen = gen + 1;
            } else {
                while (g_ggen == gen) { }
            }
        } else {
            while (g_ggen == gen) { }
        }
        __threadfence();
    }
    __syncthreads();
}

// tile geometry
#define T_ROW   144
#define T_SZ    (64 * T_ROW)          // 9216
#define ST3     (3 * T_SZ)            // decoder stage stride (ahi, bhi, blo) 27648
#define SMEM_DEC (4 * ST3)            // 110592 (4 stages)

// persistent encoder smem
#define W_TILE  (8 * T_SZ)            // 73728 (hi), lo at +W_TILE
#define A_OFF   (2 * W_TILE)          // 147456; 4 A stages x T_SZ
#define VU_OFF  (A_OFF + 4 * T_SZ)    // 184320
#define PSMEM   (VU_OFF + 2048)       // 186368

// attention smem blocking: per sub-block, 4 warps x 512 floats + maxima
#define ATT_SUB2 8320                 // 8192 (sc) + 64 (sm/sl) + pad

// ================= 16-warp 64x64 chunk MMA: D += Ah*(Bh+Bl) =================
__device__ __forceinline__ void chunk_mma_16w(uint32_t abase,
                                              uint32_t bbase, uint32_t blo_off,
                                              int mrow, int ncol, uint32_t rowsel,
                                              float acc[2][4]) {
#pragma unroll
    for (int kk = 0; kk < 4; ++kk) {
        uint32_t kof = kk * 32;
        uint32_t aaddr = abase + mrow * T_ROW + rowsel + kof;
        uint32_t baddr = bbase + ncol * T_ROW + rowsel + kof;
        uint32_t ahr[4], bh[4], bl2[4];
        ldm4(ahr, aaddr);
        ldm4(bh, baddr);
        ldm4(bl2, baddr + blo_off);
#pragma unroll
        for (int nt = 0; nt < 2; ++nt) {
            mma16816(acc[nt], ahr, bh[nt], bh[nt + 2]);
            mma16816(acc[nt], ahr, bl2[nt], bl2[nt + 2]);
        }
    }
}

// ================= 4-stage pipelined 64x64 GEMM (decoder; row stride = HH) =================
__device__ __forceinline__ void gemm_pipe(const __nv_bfloat16* __restrict__ ahi,
                                          const __nv_bfloat16* __restrict__ bhi,
                                          const __nv_bfloat16* __restrict__ blo,
                                          int kbase, int nch, uint32_t sb, int tid,
                                          int mrow, int ncol, uint32_t rowsel,
                                          float acc[2][4]) {
    int r = tid >> 3, cu = tid & 7;
    auto issue = [&](int ch) {
        if (ch < nch) {
            size_t c0 = (size_t)kbase + ch * 64 + cu * 8;
            uint32_t d = sb + (ch & 3) * ST3 + r * T_ROW + cu * 16;
            size_t ro = (size_t)r * HH + c0;
            cp16(d,            ahi + ro);
            cp16(d +     T_SZ, bhi + ro);
            cp16(d + 2 * T_SZ, blo + ro);
        }
        CP_COMMIT();
    };
    issue(0); issue(1); issue(2);
    for (int ch = 0; ch < nch; ++ch) {
        CP_WAIT2();
        __syncthreads();
        issue(ch + 3);
        uint32_t base = sb + (ch & 3) * ST3;
        chunk_mma_16w(base, base + T_SZ, T_SZ, mrow, ncol, rowsel, acc);
    }
}

// ================= persistent encoder (unchanged from R13) =================
__global__ __launch_bounds__(512) void lstm_enc_persist() {
    extern __shared__ char smem[];
    uint32_t sb = smem_u32(smem);
    int tid = threadIdx.x;
    int w = tid >> 5, l = tid & 31;
    int n0 = blockIdx.x * 64;
    int m0 = blockIdx.y * 64;
    int mgrp = blockIdx.y;
    int mrow = (w & 3) * 16;
    int ncol = (w >> 2) * 16;

    for (int i = tid; i < 4096; i += 512) {
        int c = i >> 9, r = (i >> 3) & 63, cu = i & 7;
        uint32_t d = sb + c * T_SZ + r * T_ROW + cu * 16;
        size_t src = (size_t)(n0 + r) * HH + c * 64 + cu * 8;
        cp16(d, g_Wenc_hi + src);
        cp16(d + W_TILE, g_Wenc_lo + src);
    }
    CP_COMMIT();
    float* sv = (float*)(smem + VU_OFF);
    float* su = sv + 256;
    if (tid < 256) { sv[tid] = g_v2[n0 + tid]; su[tid] = g_u2[n0 + tid]; }
    CP_WAIT0();
    __syncthreads();

    int bnew = tid >> 3;
    int kp = tid & 7;
    int b = m0 + bnew;
    int hl0 = kp * 2;
    int hbase = n0 >> 2;
    float creg[2] = {0.f, 0.f};
    uint32_t rowsel = (l & 15) * T_ROW + (l >> 4) * 16;
    int lr = tid >> 3, lcu = tid & 7;

    for (int s = 0; s < SS; ++s) {
        int par = s & 1, op = par ^ 1;
        const __nv_bfloat16* __restrict__ ah = g_hhi[par];

        float acc[2][4];
#pragma unroll
        for (int nt = 0; nt < 2; ++nt)
#pragma unroll
            for (int r = 0; r < 4; ++r) acc[nt][r] = 0.f;

        auto issueA = [&](int c) {
            if (c < 8) {
                int c0 = c * 64 + lcu * 8;
                uint32_t d = sb + A_OFF + (c & 3) * T_SZ + lr * T_ROW + lcu * 16;
                cp16(d, ah + (size_t)(m0 + lr) * HH + c0);
            }
            CP_COMMIT();
        };

        issueA(0); issueA(1); issueA(2);
        float e = g_encT[s * BB + b];
        for (int c = 0; c < 8; ++c) {
            CP_WAIT2();
            __syncthreads();
            issueA(c + 3);
            uint32_t abase = sb + A_OFF + (c & 3) * T_SZ;
            uint32_t wbase = sb + c * T_SZ;
            chunk_mma_16w(abase, wbase, W_TILE, mrow, ncol, rowsel, acc);
        }

        float* Cs = (float*)(smem + A_OFF);
        {
            int g = l >> 2, cc = l & 3;
#pragma unroll
            for (int nt = 0; nt < 2; ++nt) {
                int col = ncol + nt * 8 + cc * 2;
                int r0 = mrow + g, r1 = mrow + g + 8;
                Cs[r0 * 68 + col]     = acc[nt][0];
                Cs[r0 * 68 + col + 1] = acc[nt][1];
                Cs[r1 * 68 + col]     = acc[nt][2];
                Cs[r1 * 68 + col + 1] = acc[nt][3];
            }
        }
        __syncthreads();

        float4 c0 = *(float4*)&Cs[bnew * 68 + kp * 8];
        float4 c1 = *(float4*)&Cs[bnew * 68 + kp * 8 + 4];
        float4 v0 = *(float4*)&sv[kp * 8], v1 = *(float4*)&sv[kp * 8 + 4];
        float4 u0 = *(float4*)&su[kp * 8], u1 = *(float4*)&su[kp * 8 + 4];

        float h0, h1;
        {
            float ig = fsig(c0.x + e * v0.x + u0.x);
            float fg = fsig(c0.y + e * v0.y + u0.y);
            float gg = ftanh(c0.z + e * v0.z + u0.z);
            float og = fsig(c0.w + e * v0.w + u0.w);
            float cn = fg * creg[0] + ig * gg;
            h0 = og * ftanh(cn);
            creg[0] = cn;
        }
        {
            float ig = fsig(c1.x + e * v1.x + u1.x);
            float fg = fsig(c1.y + e * v1.y + u1.y);
            float gg = ftanh(c1.z + e * v1.z + u1.z);
            float og = fsig(c1.w + e * v1.w + u1.w);
            float cn = fg * creg[1] + ig * gg;
            h1 = og * ftanh(cn);
            creg[1] = cn;
        }
        int idx = b * HH + hbase + hl0;
        __nv_bfloat162 hi2;
        hi2.x = __float2bfloat16(h0);
        hi2.y = __float2bfloat16(h1);
        *(__nv_bfloat162*)&g_hhi[op][idx] = hi2;
        *(__nv_bfloat162*)&g_hsb[((size_t)s * BB + b) * HH + hbase + hl0] = hi2;
        if (s == SS - 1) {
            *(float2*)&g_c[idx] = make_float2(creg[0], creg[1]);
            *(float2*)&g_hbuf[op][idx] = make_float2(h0, h1);
        }
        msync(mgrp);
    }
}

// ================= persistent decoder: 96 steps, attention || gates overlap =================
__global__ __launch_bounds__(512) void dec_persist(const float* __restrict__ outW,
                                                   const float* __restrict__ outb,
                                                   float* __restrict__ out) {
    extern __shared__ char smem[];
    uint32_t sb = smem_u32(smem);
    int tid = threadIdx.x, cta = blockIdx.x;
    int w = tid >> 5, l = tid & 31;
    int mrow = (w & 3) * 16, ncol = (w >> 2) * 16;
    uint32_t rowsel = (l & 15) * T_ROW + (l >> 4) * 16;
    int g2 = l >> 2, cc = l & 3;

    for (int t = 0; t < TT; ++t) {
        int par = t & 1, op = par ^ 1;
        const __nv_bfloat16* __restrict__ ah = g_hhi[par];

        // ---------- Phase A': q2 partials, 4-way split-K (128 pieces, 1/CTA) ----------
        {
            int quarter = cta & 3;
            int idx = cta >> 2;            // 0..31
            int nq0 = (idx & 7) * 64;
            int m0 = (idx >> 3) * 64;
            float acc[2][4];
#pragma unroll
            for (int nt = 0; nt < 2; ++nt)
#pragma unroll
                for (int r = 0; r < 4; ++r) acc[nt][r] = 0.f;
            gemm_pipe(ah + (size_t)m0 * HH,
                      g_WA_hi + (size_t)(GG + nq0) * HH, g_WA_lo + (size_t)(GG + nq0) * HH,
                      quarter * 128, 2, sb, tid, mrow, ncol, rowsel, acc);
#pragma unroll
            for (int nt = 0; nt < 2; ++nt) {
                int q = nq0 + ncol + nt * 8 + cc * 2;
                int r0 = m0 + mrow + g2, r1 = r0 + 8;
                float b0 = (quarter == 0) ? g_bqk[q] : 0.f;
                float b1 = (quarter == 0) ? g_bqk[q + 1] : 0.f;
                *(float2*)(g_q2p[quarter] + r0 * HH + q) = make_float2(acc[nt][0] + b0, acc[nt][1] + b1);
                *(float2*)(g_q2p[quarter] + r1 * HH + q) = make_float2(acc[nt][2] + b0, acc[nt][3] + b1);
            }
        }
        grid_sync2(cta);

        // ---------- Phase B': CTAs 0-63 attention (4 b each) || CTAs 64-127 gates_h ----------
        if (cta < 64) {
            int sub = tid >> 7;              // 0..3
            int stid = tid & 127;
            int sw = stid >> 5, ln = stid & 31;   // 4 warps per batch
            int b = cta * 4 + sub;

            float qf[16];
            {
#pragma unroll
                for (int i = 0; i < 4; ++i) {
                    float4 va = *(const float4*)(g_q2p[0] + b * HH + ln * 16 + i * 4);
                    float4 vb = *(const float4*)(g_q2p[1] + b * HH + ln * 16 + i * 4);
                    float4 vc = *(const float4*)(g_q2p[2] + b * HH + ln * 16 + i * 4);
                    float4 vd = *(const float4*)(g_q2p[3] + b * HH + ln * 16 + i * 4);
                    qf[i * 4 + 0] = va.x + vb.x + vc.x + vd.x;
                    qf[i * 4 + 1] = va.y + vb.y + vc.y + vd.y;
                    qf[i * 4 + 2] = va.z + vb.z + vc.z + vd.z;
                    qf[i * 4 + 3] = va.w + vb.w + vc.w + vd.w;
                }
            }

            float m = -INFINITY, lsum = 0.f;
            float ca[16];
#pragma unroll
            for (int q = 0; q < 16; ++q) ca[q] = 0.f;

            const __nv_bfloat16* hb0 = g_hsb + ((size_t)sw * BB + b) * HH + ln * 16;
            uint4 u0 = *(const uint4*)hb0;
            uint4 u1 = *(const uint4*)(hb0 + 8);

#pragma unroll 4
            for (int it = 0; it < SS / 4; ++it) {
                uint4 c0 = u0, c1 = u1;
                if (it + 1 < SS / 4) {
                    const __nv_bfloat16* hb = g_hsb + ((size_t)(sw + (it + 1) * 4) * BB + b) * HH + ln * 16;
                    u0 = *(const uint4*)hb;
                    u1 = *(const uint4*)(hb + 8);
                }
                float f[16];
                {
                    const __nv_bfloat162* p0 = (const __nv_bfloat162*)&c0;
                    const __nv_bfloat162* p1 = (const __nv_bfloat162*)&c1;
#pragma unroll
                    for (int j = 0; j < 4; ++j) {
                        float2 v = __bfloat1622float2(p0[j]);
                        f[2 * j] = v.x; f[2 * j + 1] = v.y;
                        float2 v2 = __bfloat1622float2(p1[j]);
                        f[8 + 2 * j] = v2.x; f[8 + 2 * j + 1] = v2.y;
                    }
                }
                float dot = 0.f;
#pragma unroll
                for (int q = 0; q < 16; ++q) dot += f[q] * qf[q];
#pragma unroll
                for (int off = 16; off; off >>= 1) dot += __shfl_xor_sync(0xffffffffu, dot, off);
                float mn = fmaxf(m, dot);
                float scl = __expf(m - mn);
                float p = __expf(dot - mn);
                m = mn;
                lsum = lsum * scl + p;
#pragma unroll
                for (int q = 0; q < 16; ++q) ca[q] = ca[q] * scl + p * f[q];
            }

            float* sc = (float*)(smem + sub * ATT_SUB2);          // 4 x 512
            float* smx = (float*)(smem + sub * ATT_SUB2 + 8192);  // 4
            float* slx = (float*)(smem + sub * ATT_SUB2 + 8224);  // 4
#pragma unroll
            for (int q = 0; q < 16; ++q) sc[sw * HH + ln * 16 + q] = ca[q];
            if (ln == 0) { smx[sw] = m; slx[sw] = lsum; }
            __syncthreads();

            float M = smx[0];
#pragma unroll
            for (int w2 = 1; w2 < 4; ++w2) M = fmaxf(M, smx[w2]);
            float ew[4];
            float L = 0.f;
#pragma unroll
            for (int w2 = 0; w2 < 4; ++w2) { ew[w2] = __expf(smx[w2] - M); L += slx[w2] * ew[w2]; }
            float invL = __fdividef(1.f, L);
            {
                int h = stid * 4;
                float v0 = 0.f, v1 = 0.f, v2 = 0.f, v3 = 0.f;
#pragma unroll
                for (int w2 = 0; w2 < 4; ++w2) {
                    const float* r = sc + w2 * HH + h;
                    v0 += ew[w2] * r[0];
                    v1 += ew[w2] * r[1];
                    v2 += ew[w2] * r[2];
                    v3 += ew[w2] * r[3];
                }
                v0 *= invL; v1 *= invL; v2 *= invL; v3 *= invL;
                __nv_bfloat162 a2, b2;
                a2.x = __float2bfloat16(v0); a2.y = __float2bfloat16(v1);
                b2.x = __float2bfloat16(v2); b2.y = __float2bfloat16(v3);
                *(__nv_bfloat162*)&g_ctxhi[b * HH + h] = a2;
                *(__nv_bfloat162*)&g_ctxhi[b * HH + h + 2] = b2;
            }
        } else {
            // gates_h: 128 tiles, 2 per CTA
            int cta2 = cta - 64;
#pragma unroll
            for (int rep = 0; rep < 2; ++rep) {
                int id = cta2 + rep * 64;
                int n0 = (id & 31) * 64;
                int m0 = (id >> 5) * 64;
                float acc[2][4];
#pragma unroll
                for (int nt = 0; nt < 2; ++nt)
#pragma unroll
                    for (int r = 0; r < 4; ++r) acc[nt][r] = 0.f;
                gemm_pipe(ah + (size_t)m0 * HH,
                          g_WA_hi + (size_t)n0 * HH, g_WA_lo + (size_t)n0 * HH,
                          0, 8, sb, tid, mrow, ncol, rowsel, acc);
#pragma unroll
                for (int nt = 0; nt < 2; ++nt) {
                    int col = n0 + ncol + nt * 8 + cc * 2;
                    int r0 = m0 + mrow + g2, r1 = r0 + 8;
                    *(float2*)(g_gates + r0 * GG + col) = make_float2(acc[nt][0], acc[nt][1]);
                    *(float2*)(g_gates + r1 * GG + col) = make_float2(acc[nt][2], acc[nt][3]);
                }
                __syncthreads();   // drain before next rep reuses stages
            }
        }
        grid_sync2(cta);

        // ---------- Phase C: gates += ctx @ Wc^T, LSTM epilogue ----------
        {
            int n0 = (cta & 31) * 64;
            int m0 = (cta >> 5) * 64;
            float acc[2][4];
#pragma unroll
            for (int nt = 0; nt < 2; ++nt)
#pragma unroll
                for (int r = 0; r < 4; ++r) acc[nt][r] = 0.f;
            gemm_pipe(g_ctxhi + (size_t)m0 * HH,
                      g_Wc_hi + (size_t)n0 * HH, g_Wc_lo + (size_t)n0 * HH,
                      0, 8, sb, tid, mrow, ncol, rowsel, acc);

            float* Cs = (float*)smem;
            {
#pragma unroll
                for (int nt = 0; nt < 2; ++nt) {
                    int col = ncol + nt * 8 + cc * 2;
                    int r0 = mrow + g2, r1 = mrow + g2 + 8;
                    Cs[r0 * 68 + col]     = acc[nt][0];
                    Cs[r0 * 68 + col + 1] = acc[nt][1];
                    Cs[r1 * 68 + col]     = acc[nt][2];
                    Cs[r1 * 68 + col + 1] = acc[nt][3];
                }
            }
            __syncthreads();

            int bnew = tid >> 3, kp = tid & 7;
            int b = m0 + bnew;
            int hl0 = kp * 2;
            int hbase = n0 >> 2;
            int jp = n0 + kp * 8;
            float4 c0 = *(float4*)&Cs[bnew * 68 + kp * 8];
            float4 c1 = *(float4*)&Cs[bnew * 68 + kp * 8 + 4];
            float4 gr0 = *(const float4*)(g_gates + (size_t)b * GG + jp);
            float4 gr1 = *(const float4*)(g_gates + (size_t)b * GG + jp + 4);
            float4 bd0 = *(const float4*)(g_bd2 + jp);
            float4 bd1 = *(const float4*)(g_bd2 + jp + 4);
            int idx = b * HH + hbase + hl0;
            float2 cold = *(float2*)&g_c[idx];
            float h0, h1, cn0, cn1;
            {
                float ig = fsig(c0.x + gr0.x + bd0.x);
                float fg = fsig(c0.y + gr0.y + bd0.y);
                float gg = ftanh(c0.z + gr0.z + bd0.z);
                float og = fsig(c0.w + gr0.w + bd0.w);
                cn0 = fg * cold.x + ig * gg;
                h0 = og * ftanh(cn0);
            }
            {
                float ig = fsig(c1.x + gr1.x + bd1.x);
                float fg = fsig(c1.y + gr1.y + bd1.y);
                float gg = ftanh(c1.z + gr1.z + bd1.z);
                float og = fsig(c1.w + gr1.w + bd1.w);
                cn1 = fg * cold.y + ig * gg;
                h1 = og * ftanh(cn1);
            }
            *(float2*)&g_c[idx] = make_float2(cn0, cn1);
            *(float2*)&g_hbuf[op][idx] = make_float2(h0, h1);
            __nv_bfloat162 hi2;
            hi2.x = __float2bfloat16(h0);
            hi2.y = __float2bfloat16(h1);
            *(__nv_bfloat162*)&g_hhi[op][idx] = hi2;
        }
        grid_sync2(cta);

        // ---------- Phase D: output projection ----------
        if (w < 2) {
            int b = cta * 2 + w;
            const float* hp = g_hbuf[op] + b * HH;
            float p = 0.f;
#pragma unroll
            for (int q = 0; q < 16; ++q) p += hp[l + (q << 5)] * outW[l + (q << 5)];
#pragma unroll
            for (int off = 16; off; off >>= 1) p += __shfl_xor_sync(0xffffffffu, p, off);
            if (l == 0) out[b * TT + t] = p + outb[0];
        }
    }
}

// ================= prep (3 launches total) =================
__global__ void k_prep1(const float* __restrict__ embW, const float* __restrict__ embb,
                        const float* __restrict__ encWih, const float* __restrict__ encbih,
                        const float* __restrict__ encbhh, const float* __restrict__ encWhh,
                        const float* __restrict__ dWih, const float* __restrict__ dWhh,
                        const float* __restrict__ dbih, const float* __restrict__ dbhh) {
    int idx = blockIdx.x * 256 + threadIdx.x;
    {
        int jp = idx >> 9, k = idx & (HH - 1);
        int h = jp >> 2, g = jp & 3;
        float we = encWhh[(g * HH + h) * HH + k];
        __nv_bfloat16 hie = __float2bfloat16(we);
        g_Wenc_hi[idx] = hie;
        g_Wenc_lo[idx] = __float2bfloat16(we - __bfloat162float(hie));
        float wa = dWih[(g * HH + h) * K2 + k] + dWhh[(g * HH + h) * HH + k];
        __nv_bfloat16 hia = __float2bfloat16(wa);
        g_WA_hi[idx] = hia;
        g_WA_lo[idx] = __float2bfloat16(wa - __bfloat162float(hia));
        float wc = dWih[(g * HH + h) * K2 + HH + k];
        __nv_bfloat16 hic = __float2bfloat16(wc);
        g_Wc_hi[idx] = hic;
        g_Wc_lo[idx] = __float2bfloat16(wc - __bfloat162float(hic));
    }
    if (idx < GG) {
        int h = idx >> 2, g = idx & 3;
        int j = g * HH + h;
        float v = 0.f, u = 0.f;
        const float* wr = encWih + j * RR;
#pragma unroll 8
        for (int r = 0; r < RR; ++r) { v += embW[r] * wr[r]; u += embb[r] * wr[r]; }
        g_v2[idx] = v;
        g_u2[idx] = u + encbih[j] + encbhh[j];
        g_bd2[idx] = dbih[j] + dbhh[j];
    }
    if (idx < BB * HH) {
        g_hhi[0][idx] = __float2bfloat16(0.f);
    }
}

// P2: transposes. z=0: Wk->WkT, z=1: Wq->WqT, z=2: enc_inputs [B,S]->g_encT [S,B]
__global__ void k_prep2(const float* __restrict__ Wk, const float* __restrict__ Wq,
                        const float* __restrict__ encIn) {
    __shared__ float t[32][33];
    int z = blockIdx.z;
    if (z == 2 && blockIdx.y >= 8) return;
    const float* in = (z == 0) ? Wk : (z == 1) ? Wq : encIn;
    float* outp = (z == 0) ? g_WkT : (z == 1) ? g_WqT : g_encT;
    int in_cols = (z == 2) ? SS : HH;
    int out_cols = (z == 2) ? BB : HH;
    int x = blockIdx.x * 32 + threadIdx.x;
    int y0 = blockIdx.y * 32;
    for (int j = threadIdx.y; j < 32; j += 8) t[j][threadIdx.x] = in[(y0 + j) * in_cols + x];
    __syncthreads();
    int x2 = y0 + threadIdx.x;
    int y20 = blockIdx.x * 32;
    for (int j = threadIdx.y; j < 32; j += 8) outp[(y20 + j) * out_cols + x2] = t[threadIdx.x][j];
}

__global__ __launch_bounds__(256) void k_prep3(const float* __restrict__ bq) {
    __shared__ float As[32][33];
    __shared__ float Bs[32][33];
    int tid = threadIdx.x;
    int m0 = blockIdx.y * 32, n0 = blockIdx.x * 32;
    int lr = tid >> 3, lk = (tid & 7) << 2;
    int ty = tid >> 4, tx = tid & 15;
    float acc00 = 0.f, acc01 = 0.f, acc10 = 0.f, acc11 = 0.f;
    for (int kk = 0; kk < HH; kk += 32) {
        float4 a = *(const float4*)(g_WkT + (m0 + lr) * HH + kk + lk);
        float4 b = *(const float4*)(g_WqT + (n0 + lr) * HH + kk + lk);
        __syncthreads();
        As[lk + 0][lr] = a.x; As[lk + 1][lr] = a.y; As[lk + 2][lr] = a.z; As[lk + 3][lr] = a.w;
        Bs[lk + 0][lr] = b.x; Bs[lk + 1][lr] = b.y; Bs[lk + 2][lr] = b.z; Bs[lk + 3][lr] = b.w;
        __syncthreads();
#pragma unroll
        for (int k = 0; k < 32; ++k) {
            float a0 = As[k][ty * 2], a1 = As[k][ty * 2 + 1];
            float b0 = Bs[k][tx * 2], b1 = Bs[k][tx * 2 + 1];
            acc00 += a0 * b0; acc01 += a0 * b1;
            acc10 += a1 * b0; acc11 += a1 * b1;
        }
    }
    auto wr = [&](int m, int p, float v) {
        size_t d = (size_t)(GG + m) * HH + p;
        __nv_bfloat16 hi = __float2bfloat16(v);
        g_WA_hi[d] = hi;
        g_WA_lo[d] = __float2bfloat16(v - __bfloat162float(hi));
    };
    wr(m0 + ty * 2 + 0, n0 + tx * 2 + 0, acc00);
    wr(m0 + ty * 2 + 0, n0 + tx * 2 + 1, acc01);
    wr(m0 + ty * 2 + 1, n0 + tx * 2 + 0, acc10);
    wr(m0 + ty * 2 + 1, n0 + tx * 2 + 1, acc11);

    if (blockIdx.x == 0) {
        int wv = tid >> 5, ln = tid & 31;
#pragma unroll
        for (int it = 0; it < 4; ++it) {
            int m = m0 + wv + it * 8;
            const float* row = g_WkT + (size_t)m * HH;
            float a = 0.f;
            for (int n = ln; n < HH; n += 32) a += bq[n] * row[n];
#pragma unroll
            for (int off = 16; off; off >>= 1) a += __shfl_xor_sync(0xffffffffu, a, off);
            if (ln == 0) g_bqk[m] = a;
        }
    }
}

// ---------------- host launcher ----------------
extern "C" void kernel_launch(void* const* d_in, const int* in_sizes, int n_in,
                              void* d_out, int out_size) {
    int off = (n_in >= 18 && in_sizes[1] == 1) ? 1 : 0;
    const float* enc_inputs = (const float*)d_in[0];
    const float* embed_W = (const float*)d_in[1 + off];
    const float* embed_b = (const float*)d_in[2 + off];
    const float* enc_Wih = (const float*)d_in[3 + off];
    const float* enc_Whh = (const float*)d_in[4 + off];
    const float* enc_bih = (const float*)d_in[5 + off];
    const float* enc_bhh = (const float*)d_in[6 + off];
    const float* dec_Wih = (const float*)d_in[7 + off];
    const float* dec_Whh = (const float*)d_in[8 + off];
    const float* dec_bih = (const float*)d_in[9 + off];
    const float* dec_bhh = (const float*)d_in[10 + off];
    const float* Wq = (const float*)d_in[11 + off];
    const float* bq = (const float*)d_in[12 + off];
    const float* Wk = (const float*)d_in[13 + off];
    // bk dropped: uniform over s -> softmax-invariant
    const float* out_W = (const float*)d_in[15 + off];
    const float* out_b = (const float*)d_in[16 + off];
    float* out = (float*)d_out;

    cudaFuncSetAttribute(lstm_enc_persist, cudaFuncAttributeMaxDynamicSharedMemorySize, PSMEM);
    cudaFuncSetAttribute(dec_persist, cudaFuncAttributeMaxDynamicSharedMemorySize, SMEM_DEC);

    // ---- prep: exactly 3 launches ----
    k_prep1<<<(GG * HH) / 256, 256>>>(embed_W, embed_b, enc_Wih, enc_bih, enc_bhh,
                                      enc_Whh, dec_Wih, dec_Whh, dec_bih, dec_bhh);
    dim3 tb(32, 8);
    k_prep2<<<dim3(16, 16, 3), tb>>>(Wk, Wq, enc_inputs);
    k_prep3<<<dim3(16, 16), 256>>>(bq);

    // ---- encoder: ONE persistent kernel ----
    lstm_enc_persist<<<dim3(32, 4), 512, PSMEM>>>();

    // ---- decoder: ONE persistent kernel ----
    dec_persist<<<128, 512, SMEM_DEC>>>(out_W, out_b, out);

    (void)in_sizes; (void)n_in; (void)out_size;
}

// round 15
// speedup vs baseline: 1.2841x; 1.2841x over previous
#include <cuda_runtime.h>
#include <cuda_bf16.h>
#include <math.h>
#include <stdint.h>

#define BB 256
#define SS 512
#define RR 128
#define HH 512
#define TT 96
#define GG 2048   // 4*H
#define K2 1024   // 2*H

// ---------------- device scratch ----------------
__device__ __nv_bfloat16 g_hsb[(size_t)SS * BB * HH];   // encoder hidden states bf16 [s][b][h]
__device__ float g_hbuf[2][BB * HH];                    // ping-pong hidden fp32 (for out proj)
__device__ float g_c[BB * HH];                          // cell state fp32 (decoder)
__device__ __nv_bfloat16 g_hhi[2][BB * HH];             // bf16 h ping-pong (hi only)
__device__ __nv_bfloat16 g_ctxhi[BB * HH];              // bf16 context (hi only)
__device__ __nv_bfloat16 g_Wenc_hi[GG * HH],  g_Wenc_lo[GG * HH];
__device__ __nv_bfloat16 g_WA_hi[(GG + HH) * HH], g_WA_lo[(GG + HH) * HH]; // [gates_h | At]
__device__ __nv_bfloat16 g_Wc_hi[GG * HH], g_Wc_lo[GG * HH];               // ctx half of dec Wih
__device__ float g_gates[BB * GG];                     // cached gates_h (fp32)
__device__ float g_q2p[4][BB * HH];                    // q2 split-K partials (4-way)
__device__ float g_v2[GG], g_u2[GG], g_bd2[GG];
__device__ float g_WkT[HH * HH], g_WqT[HH * HH];
__device__ float g_bqk[HH];
__device__ float g_encT[SS * BB];                      // enc_inputs transposed [s][b]

// ---- encoder per-m-group barriers (4 groups x 32 CTAs) ----
__device__ unsigned g_mbar_count[4] = {0, 0, 0, 0};
__device__ volatile unsigned g_mbar_gen[4] = {0, 0, 0, 0};

// ---- decoder 2-level tree barrier (8 groups x 16 CTAs -> root of 8) ----
__device__ unsigned g_gcount[8] = {0, 0, 0, 0, 0, 0, 0, 0};
__device__ unsigned g_rcount = 0;
__device__ volatile unsigned g_ggen = 0;

// ---------------- helpers ----------------
__device__ __forceinline__ uint32_t smem_u32(const void* p) {
    uint32_t a;
    asm("{ .reg .u64 t; cvta.to.shared.u64 t, %1; cvt.u32.u64 %0, t; }" : "=r"(a) : "l"(p));
    return a;
}
__device__ __forceinline__ void cp16(uint32_t dst, const void* src) {
    asm volatile("cp.async.cg.shared.global [%0], [%1], 16;" :: "r"(dst), "l"(src) : "memory");
}
#define CP_COMMIT() asm volatile("cp.async.commit_group;" ::: "memory")
#define CP_WAIT2()  asm volatile("cp.async.wait_group 2;" ::: "memory")
#define CP_WAIT0()  asm volatile("cp.async.wait_group 0;" ::: "memory")

__device__ __forceinline__ void ldm4(uint32_t* r, uint32_t addr) {
    asm volatile("ldmatrix.sync.aligned.m8n8.x4.shared.b16 {%0,%1,%2,%3}, [%4];"
                 : "=r"(r[0]), "=r"(r[1]), "=r"(r[2]), "=r"(r[3]) : "r"(addr));
}
__device__ __forceinline__ void mma16816(float* c, const uint32_t* a, uint32_t b0, uint32_t b1) {
    asm volatile(
        "mma.sync.aligned.m16n8k16.row.col.f32.bf16.bf16.f32 "
        "{%0,%1,%2,%3}, {%4,%5,%6,%7}, {%8,%9}, {%0,%1,%2,%3};"
        : "+f"(c[0]), "+f"(c[1]), "+f"(c[2]), "+f"(c[3])
        : "r"(a[0]), "r"(a[1]), "r"(a[2]), "r"(a[3]), "r"(b0), "r"(b1));
}

// fast sigmoid/tanh (~2ulp via __expf)
__device__ __forceinline__ float fsig(float x) {
    return __fdividef(1.f, 1.f + __expf(-x));
}
__device__ __forceinline__ float ftanh(float x) {
    float e = __expf(2.f * x);
    return 1.f - __fdividef(2.f, e + 1.f);
}

// encoder: per-m-group barrier (32 CTAs sharing blockIdx.y)
__device__ __forceinline__ void msync(int grp) {
    __syncthreads();
    if (threadIdx.x == 0) {
        __threadfence();
        unsigned gen = g_mbar_gen[grp];
        unsigned t = atomicInc(&g_mbar_count[grp], 31);
        if (t == 31) {
            g_mbar_gen[grp] = gen + 1;
        } else {
            while (g_mbar_gen[grp] == gen) { }
        }
        __threadfence();
    }
    __syncthreads();
}

// decoder: 2-level tree barrier across 128 CTAs
__device__ __forceinline__ void grid_sync2(int cta) {
    __syncthreads();
    if (threadIdx.x == 0) {
        __threadfence();
        unsigned gen = g_ggen;
        unsigned t = atomicInc(&g_gcount[cta >> 4], 15);
        if (t == 15) {
            unsigned r = atomicInc(&g_rcount, 7);
            if (r == 7) {
                g_ggen = gen + 1;
            } else {
                while (g_ggen == gen) { }
            }
        } else {
            while (g_ggen == gen) { }
        }
        __threadfence();
    }
    __syncthreads();
}

// tile geometry
#define T_ROW   144
#define T_SZ    (64 * T_ROW)          // 9216
#define ST3     (3 * T_SZ)            // decoder stage stride (ahi, bhi, blo) 27648
#define SMEM_DEC (4 * ST3)            // 110592 (4 stages)

// persistent encoder smem
#define W_TILE  (8 * T_SZ)            // 73728 (hi), lo at +W_TILE
#define A_OFF   (2 * W_TILE)          // 147456; 4 A stages x T_SZ
#define VU_OFF  (A_OFF + 4 * T_SZ)    // 184320
#define PSMEM   (VU_OFF + 2048)       // 186368

// attention phase smem blocking
#define ATT_SUB 16640                 // sc 16384 + sm 32 + sl 32 (padded)

// ================= 16-warp 64x64 chunk MMA: D += Ah*(Bh+Bl) =================
__device__ __forceinline__ void chunk_mma_16w(uint32_t abase,
                                              uint32_t bbase, uint32_t blo_off,
                                              int mrow, int ncol, uint32_t rowsel,
                                              float acc[2][4]) {
#pragma unroll
    for (int kk = 0; kk < 4; ++kk) {
        uint32_t kof = kk * 32;
        uint32_t aaddr = abase + mrow * T_ROW + rowsel + kof;
        uint32_t baddr = bbase + ncol * T_ROW + rowsel + kof;
        uint32_t ahr[4], bh[4], bl2[4];
        ldm4(ahr, aaddr);
        ldm4(bh, baddr);
        ldm4(bl2, baddr + blo_off);
#pragma unroll
        for (int nt = 0; nt < 2; ++nt) {
            mma16816(acc[nt], ahr, bh[nt], bh[nt + 2]);
            mma16816(acc[nt], ahr, bl2[nt], bl2[nt + 2]);
        }
    }
}

// ================= 4-stage pipelined 64x64 GEMM (decoder; row stride = HH) =================
__device__ __forceinline__ void gemm_pipe(const __nv_bfloat16* __restrict__ ahi,
                                          const __nv_bfloat16* __restrict__ bhi,
                                          const __nv_bfloat16* __restrict__ blo,
                                          int kbase, int nch, uint32_t sb, int tid,
                                          int mrow, int ncol, uint32_t rowsel,
                                          float acc[2][4]) {
    int r = tid >> 3, cu = tid & 7;
    auto issue = [&](int ch) {
        if (ch < nch) {
            size_t c0 = (size_t)kbase + ch * 64 + cu * 8;
            uint32_t d = sb + (ch & 3) * ST3 + r * T_ROW + cu * 16;
            size_t ro = (size_t)r * HH + c0;
            cp16(d,            ahi + ro);
            cp16(d +     T_SZ, bhi + ro);
            cp16(d + 2 * T_SZ, blo + ro);
        }
        CP_COMMIT();
    };
    issue(0); issue(1); issue(2);
    for (int ch = 0; ch < nch; ++ch) {
        CP_WAIT2();
        __syncthreads();
        issue(ch + 3);
        uint32_t base = sb + (ch & 3) * ST3;
        chunk_mma_16w(base, base + T_SZ, T_SZ, mrow, ncol, rowsel, acc);
    }
}

// ================= persistent encoder (R13, unchanged) =================
__global__ __launch_bounds__(512) void lstm_enc_persist() {
    extern __shared__ char smem[];
    uint32_t sb = smem_u32(smem);
    int tid = threadIdx.x;
    int w = tid >> 5, l = tid & 31;
    int n0 = blockIdx.x * 64;
    int m0 = blockIdx.y * 64;
    int mgrp = blockIdx.y;
    int mrow = (w & 3) * 16;
    int ncol = (w >> 2) * 16;

    for (int i = tid; i < 4096; i += 512) {
        int c = i >> 9, r = (i >> 3) & 63, cu = i & 7;
        uint32_t d = sb + c * T_SZ + r * T_ROW + cu * 16;
        size_t src = (size_t)(n0 + r) * HH + c * 64 + cu * 8;
        cp16(d, g_Wenc_hi + src);
        cp16(d + W_TILE, g_Wenc_lo + src);
    }
    CP_COMMIT();
    float* sv = (float*)(smem + VU_OFF);
    float* su = sv + 256;
    if (tid < 256) { sv[tid] = g_v2[n0 + tid]; su[tid] = g_u2[n0 + tid]; }
    CP_WAIT0();
    __syncthreads();

    int bnew = tid >> 3;
    int kp = tid & 7;
    int b = m0 + bnew;
    int hl0 = kp * 2;
    int hbase = n0 >> 2;
    float creg[2] = {0.f, 0.f};
    uint32_t rowsel = (l & 15) * T_ROW + (l >> 4) * 16;
    int lr = tid >> 3, lcu = tid & 7;

    for (int s = 0; s < SS; ++s) {
        int par = s & 1, op = par ^ 1;
        const __nv_bfloat16* __restrict__ ah = g_hhi[par];

        float acc[2][4];
#pragma unroll
        for (int nt = 0; nt < 2; ++nt)
#pragma unroll
            for (int r = 0; r < 4; ++r) acc[nt][r] = 0.f;

        auto issueA = [&](int c) {
            if (c < 8) {
                int c0 = c * 64 + lcu * 8;
                uint32_t d = sb + A_OFF + (c & 3) * T_SZ + lr * T_ROW + lcu * 16;
                cp16(d, ah + (size_t)(m0 + lr) * HH + c0);
            }
            CP_COMMIT();
        };

        issueA(0); issueA(1); issueA(2);
        float e = g_encT[s * BB + b];
        for (int c = 0; c < 8; ++c) {
            CP_WAIT2();
            __syncthreads();
            issueA(c + 3);
            uint32_t abase = sb + A_OFF + (c & 3) * T_SZ;
            uint32_t wbase = sb + c * T_SZ;
            chunk_mma_16w(abase, wbase, W_TILE, mrow, ncol, rowsel, acc);
        }

        float* Cs = (float*)(smem + A_OFF);
        {
            int g = l >> 2, cc = l & 3;
#pragma unroll
            for (int nt = 0; nt < 2; ++nt) {
                int col = ncol + nt * 8 + cc * 2;
                int r0 = mrow + g, r1 = mrow + g + 8;
                Cs[r0 * 68 + col]     = acc[nt][0];
                Cs[r0 * 68 + col + 1] = acc[nt][1];
                Cs[r1 * 68 + col]     = acc[nt][2];
                Cs[r1 * 68 + col + 1] = acc[nt][3];
            }
        }
        __syncthreads();

        float4 c0 = *(float4*)&Cs[bnew * 68 + kp * 8];
        float4 c1 = *(float4*)&Cs[bnew * 68 + kp * 8 + 4];
        float4 v0 = *(float4*)&sv[kp * 8], v1 = *(float4*)&sv[kp * 8 + 4];
        float4 u0 = *(float4*)&su[kp * 8], u1 = *(float4*)&su[kp * 8 + 4];

        float h0, h1;
        {
            float ig = fsig(c0.x + e * v0.x + u0.x);
            float fg = fsig(c0.y + e * v0.y + u0.y);
            float gg = ftanh(c0.z + e * v0.z + u0.z);
            float og = fsig(c0.w + e * v0.w + u0.w);
            float cn = fg * creg[0] + ig * gg;
            h0 = og * ftanh(cn);
            creg[0] = cn;
        }
        {
            float ig = fsig(c1.x + e * v1.x + u1.x);
            float fg = fsig(c1.y + e * v1.y + u1.y);
            float gg = ftanh(c1.z + e * v1.z + u1.z);
            float og = fsig(c1.w + e * v1.w + u1.w);
            float cn = fg * creg[1] + ig * gg;
            h1 = og * ftanh(cn);
            creg[1] = cn;
        }
        int idx = b * HH + hbase + hl0;
        __nv_bfloat162 hi2;
        hi2.x = __float2bfloat16(h0);
        hi2.y = __float2bfloat16(h1);
        *(__nv_bfloat162*)&g_hhi[op][idx] = hi2;
        *(__nv_bfloat162*)&g_hsb[((size_t)s * BB + b) * HH + hbase + hl0] = hi2;
        if (s == SS - 1) {
            *(float2*)&g_c[idx] = make_float2(creg[0], creg[1]);
            *(float2*)&g_hbuf[op][idx] = make_float2(h0, h1);
        }
        msync(mgrp);
    }
}

// ================= persistent decoder: 96 steps (R13 + depth-2 attention prefetch) =================
__global__ __launch_bounds__(512) void dec_persist(const float* __restrict__ outW,
                                                   const float* __restrict__ outb,
                                                   float* __restrict__ out) {
    extern __shared__ char smem[];
    uint32_t sb = smem_u32(smem);
    int tid = threadIdx.x, cta = blockIdx.x;
    int w = tid >> 5, l = tid & 31;
    int mrow = (w & 3) * 16, ncol = (w >> 2) * 16;
    uint32_t rowsel = (l & 15) * T_ROW + (l >> 4) * 16;
    int g2 = l >> 2, cc = l & 3;

    for (int t = 0; t < TT; ++t) {
        int par = t & 1, op = par ^ 1;
        const __nv_bfloat16* __restrict__ ah = g_hhi[par];

        // ---------- Phase A round 1: gates_h (128 tiles, 1/CTA) ----------
        {
            int n0 = (cta & 31) * 64;
            int m0 = (cta >> 5) * 64;
            float acc[2][4];
#pragma unroll
            for (int nt = 0; nt < 2; ++nt)
#pragma unroll
                for (int r = 0; r < 4; ++r) acc[nt][r] = 0.f;
            gemm_pipe(ah + (size_t)m0 * HH,
                      g_WA_hi + (size_t)n0 * HH, g_WA_lo + (size_t)n0 * HH,
                      0, 8, sb, tid, mrow, ncol, rowsel, acc);
#pragma unroll
            for (int nt = 0; nt < 2; ++nt) {
                int col = n0 + ncol + nt * 8 + cc * 2;
                int r0 = m0 + mrow + g2, r1 = r0 + 8;
                *(float2*)(g_gates + r0 * GG + col) = make_float2(acc[nt][0], acc[nt][1]);
                *(float2*)(g_gates + r1 * GG + col) = make_float2(acc[nt][2], acc[nt][3]);
            }
        }

        // ---------- Phase A round 2: q2 partials, 4-way split-K ----------
        {
            int quarter = cta & 3;
            int idx = cta >> 2;            // 0..31
            int nq0 = (idx & 7) * 64;
            int m0 = (idx >> 3) * 64;
            float acc[2][4];
#pragma unroll
            for (int nt = 0; nt < 2; ++nt)
#pragma unroll
                for (int r = 0; r < 4; ++r) acc[nt][r] = 0.f;
            gemm_pipe(ah + (size_t)m0 * HH,
                      g_WA_hi + (size_t)(GG + nq0) * HH, g_WA_lo + (size_t)(GG + nq0) * HH,
                      quarter * 128, 2, sb, tid, mrow, ncol, rowsel, acc);
#pragma unroll
            for (int nt = 0; nt < 2; ++nt) {
                int q = nq0 + ncol + nt * 8 + cc * 2;
                int r0 = m0 + mrow + g2, r1 = r0 + 8;
                float b0 = (quarter == 0) ? g_bqk[q] : 0.f;
                float b1 = (quarter == 0) ? g_bqk[q + 1] : 0.f;
                *(float2*)(g_q2p[quarter] + r0 * HH + q) = make_float2(acc[nt][0] + b0, acc[nt][1] + b1);
                *(float2*)(g_q2p[quarter] + r1 * HH + q) = make_float2(acc[nt][2] + b0, acc[nt][3] + b1);
            }
        }
        grid_sync2(cta);

        // ---------- Phase B: attention, 2 batches per CTA, depth-2 prefetch ----------
        {
            int sub = tid >> 8, stid = tid & 255;
            int sw = stid >> 5, ln = stid & 31;
            int b = cta * 2 + sub;

            float qf[16];
            {
#pragma unroll
                for (int i = 0; i < 4; ++i) {
                    float4 va = *(const float4*)(g_q2p[0] + b * HH + ln * 16 + i * 4);
                    float4 vb = *(const float4*)(g_q2p[1] + b * HH + ln * 16 + i * 4);
                    float4 vc = *(const float4*)(g_q2p[2] + b * HH + ln * 16 + i * 4);
                    float4 vd = *(const float4*)(g_q2p[3] + b * HH + ln * 16 + i * 4);
                    qf[i * 4 + 0] = va.x + vb.x + vc.x + vd.x;
                    qf[i * 4 + 1] = va.y + vb.y + vc.y + vd.y;
                    qf[i * 4 + 2] = va.z + vb.z + vc.z + vd.z;
                    qf[i * 4 + 3] = va.w + vb.w + vc.w + vd.w;
                }
            }

            float m = -INFINITY, lsum = 0.f;
            float ca[16];
#pragma unroll
            for (int q = 0; q < 16; ++q) ca[q] = 0.f;

            const __nv_bfloat16* base = g_hsb + (size_t)b * HH + (size_t)ln * 16;
            // depth-2 prefetch ring
            uint4 p0[2], p1[2];
            {
                const __nv_bfloat16* hb = base + (size_t)(sw + 0 * 8) * BB * HH;
                p0[0] = *(const uint4*)hb; p1[0] = *(const uint4*)(hb + 8);
                hb = base + (size_t)(sw + 1 * 8) * BB * HH;
                p0[1] = *(const uint4*)hb; p1[1] = *(const uint4*)(hb + 8);
            }

#pragma unroll 4
            for (int it = 0; it < SS / 8; ++it) {
                int slot = it & 1;
                uint4 c0 = p0[slot], c1 = p1[slot];
                if (it + 2 < SS / 8) {
                    const __nv_bfloat16* hb = base + (size_t)(sw + (it + 2) * 8) * BB * HH;
                    p0[slot] = *(const uint4*)hb;
                    p1[slot] = *(const uint4*)(hb + 8);
                }
                float f[16];
                {
                    const __nv_bfloat162* q0 = (const __nv_bfloat162*)&c0;
                    const __nv_bfloat162* q1 = (const __nv_bfloat162*)&c1;
#pragma unroll
                    for (int j = 0; j < 4; ++j) {
                        float2 v = __bfloat1622float2(q0[j]);
                        f[2 * j] = v.x; f[2 * j + 1] = v.y;
                        float2 v2 = __bfloat1622float2(q1[j]);
                        f[8 + 2 * j] = v2.x; f[8 + 2 * j + 1] = v2.y;
                    }
                }
                float dot = 0.f;
#pragma unroll
                for (int q = 0; q < 16; ++q) dot += f[q] * qf[q];
#pragma unroll
                for (int off = 16; off; off >>= 1) dot += __shfl_xor_sync(0xffffffffu, dot, off);
                float mn = fmaxf(m, dot);
                float scl = __expf(m - mn);
                float p = __expf(dot - mn);
                m = mn;
                lsum = lsum * scl + p;
#pragma unroll
                for (int q = 0; q < 16; ++q) ca[q] = ca[q] * scl + p * f[q];
            }

            float* sc = (float*)(smem + sub * ATT_SUB);
            float* smx = (float*)(smem + sub * ATT_SUB + 16384);
            float* slx = (float*)(smem + sub * ATT_SUB + 16416);
#pragma unroll
            for (int q = 0; q < 16; ++q) sc[sw * HH + ln * 16 + q] = ca[q];
            if (ln == 0) { smx[sw] = m; slx[sw] = lsum; }
            __syncthreads();

            float M = smx[0];
#pragma unroll
            for (int w2 = 1; w2 < 8; ++w2) M = fmaxf(M, smx[w2]);
            float ew[8];
            float L = 0.f;
#pragma unroll
            for (int w2 = 0; w2 < 8; ++w2) { ew[w2] = __expf(smx[w2] - M); L += slx[w2] * ew[w2]; }
            float invL = __fdividef(1.f, L);
            {
                int h = stid * 2;
                float va = 0.f, vb = 0.f;
#pragma unroll
                for (int w2 = 0; w2 < 8; ++w2) {
                    va += ew[w2] * sc[w2 * HH + h];
                    vb += ew[w2] * sc[w2 * HH + h + 1];
                }
                va *= invL; vb *= invL;
                __nv_bfloat162 hi2;
                hi2.x = __float2bfloat16(va);
                hi2.y = __float2bfloat16(vb);
                *(__nv_bfloat162*)&g_ctxhi[b * HH + h] = hi2;
            }
        }
        grid_sync2(cta);

        // ---------- Phase C: gates += ctx @ Wc^T, LSTM epilogue ----------
        {
            int n0 = (cta & 31) * 64;
            int m0 = (cta >> 5) * 64;
            float acc[2][4];
#pragma unroll
            for (int nt = 0; nt < 2; ++nt)
#pragma unroll
                for (int r = 0; r < 4; ++r) acc[nt][r] = 0.f;
            gemm_pipe(g_ctxhi + (size_t)m0 * HH,
                      g_Wc_hi + (size_t)n0 * HH, g_Wc_lo + (size_t)n0 * HH,
                      0, 8, sb, tid, mrow, ncol, rowsel, acc);

            float* Cs = (float*)smem;
            {
#pragma unroll
                for (int nt = 0; nt < 2; ++nt) {
                    int col = ncol + nt * 8 + cc * 2;
                    int r0 = mrow + g2, r1 = mrow + g2 + 8;
                    Cs[r0 * 68 + col]     = acc[nt][0];
                    Cs[r0 * 68 + col + 1] = acc[nt][1];
                    Cs[r1 * 68 + col]     = acc[nt][2];
                    Cs[r1 * 68 + col + 1] = acc[nt][3];
                }
            }
            __syncthreads();

            int bnew = tid >> 3, kp = tid & 7;
            int b = m0 + bnew;
            int hl0 = kp * 2;
            int hbase = n0 >> 2;
            int jp = n0 + kp * 8;
            float4 c0 = *(float4*)&Cs[bnew * 68 + kp * 8];
            float4 c1 = *(float4*)&Cs[bnew * 68 + kp * 8 + 4];
            float4 gr0 = *(const float4*)(g_gates + (size_t)b * GG + jp);
            float4 gr1 = *(const float4*)(g_gates + (size_t)b * GG + jp + 4);
            float4 bd0 = *(const float4*)(g_bd2 + jp);
            float4 bd1 = *(const float4*)(g_bd2 + jp + 4);
            int idx = b * HH + hbase + hl0;
            float2 cold = *(float2*)&g_c[idx];
            float h0, h1, cn0, cn1;
            {
                float ig = fsig(c0.x + gr0.x + bd0.x);
                float fg = fsig(c0.y + gr0.y + bd0.y);
                float gg = ftanh(c0.z + gr0.z + bd0.z);
                float og = fsig(c0.w + gr0.w + bd0.w);
                cn0 = fg * cold.x + ig * gg;
                h0 = og * ftanh(cn0);
            }
            {
                float ig = fsig(c1.x + gr1.x + bd1.x);
                float fg = fsig(c1.y + gr1.y + bd1.y);
                float gg = ftanh(c1.z + gr1.z + bd1.z);
                float og = fsig(c1.w + gr1.w + bd1.w);
                cn1 = fg * cold.y + ig * gg;
                h1 = og * ftanh(cn1);
            }
            *(float2*)&g_c[idx] = make_float2(cn0, cn1);
            *(float2*)&g_hbuf[op][idx] = make_float2(h0, h1);
            __nv_bfloat162 hi2;
            hi2.x = __float2bfloat16(h0);
            hi2.y = __float2bfloat16(h1);
            *(__nv_bfloat162*)&g_hhi[op][idx] = hi2;
        }
        grid_sync2(cta);

        // ---------- Phase D: output projection ----------
        if (w < 2) {
            int b = cta * 2 + w;
            const float* hp = g_hbuf[op] + b * HH;
            float p = 0.f;
#pragma unroll
            for (int q = 0; q < 16; ++q) p += hp[l + (q << 5)] * outW[l + (q << 5)];
#pragma unroll
            for (int off = 16; off; off >>= 1) p += __shfl_xor_sync(0xffffffffu, p, off);
            if (l == 0) out[b * TT + t] = p + outb[0];
        }
    }
}

// ================= prep (3 launches total) =================
__global__ void k_prep1(const float* __restrict__ embW, const float* __restrict__ embb,
                        const float* __restrict__ encWih, const float* __restrict__ encbih,
                        const float* __restrict__ encbhh, const float* __restrict__ encWhh,
                        const float* __restrict__ dWih, const float* __restrict__ dWhh,
                        const float* __restrict__ dbih, const float* __restrict__ dbhh) {
    int idx = blockIdx.x * 256 + threadIdx.x;
    {
        int jp = idx >> 9, k = idx & (HH - 1);
        int h = jp >> 2, g = jp & 3;
        float we = encWhh[(g * HH + h) * HH + k];
        __nv_bfloat16 hie = __float2bfloat16(we);
        g_Wenc_hi[idx] = hie;
        g_Wenc_lo[idx] = __float2bfloat16(we - __bfloat162float(hie));
        float wa = dWih[(g * HH + h) * K2 + k] + dWhh[(g * HH + h) * HH + k];
        __nv_bfloat16 hia = __float2bfloat16(wa);
        g_WA_hi[idx] = hia;
        g_WA_lo[idx] = __float2bfloat16(wa - __bfloat162float(hia));
        float wc = dWih[(g * HH + h) * K2 + HH + k];
        __nv_bfloat16 hic = __float2bfloat16(wc);
        g_Wc_hi[idx] = hic;
        g_Wc_lo[idx] = __float2bfloat16(wc - __bfloat162float(hic));
    }
    if (idx < GG) {
        int h = idx >> 2, g = idx & 3;
        int j = g * HH + h;
        float v = 0.f, u = 0.f;
        const float* wr = encWih + j * RR;
#pragma unroll 8
        for (int r = 0; r < RR; ++r) { v += embW[r] * wr[r]; u += embb[r] * wr[r]; }
        g_v2[idx] = v;
        g_u2[idx] = u + encbih[j] + encbhh[j];
        g_bd2[idx] = dbih[j] + dbhh[j];
    }
    if (idx < BB * HH) {
        g_hhi[0][idx] = __float2bfloat16(0.f);
    }
}

// P2: transposes. z=0: Wk->WkT, z=1: Wq->WqT, z=2: enc_inputs [B,S]->g_encT [S,B]
__global__ void k_prep2(const float* __restrict__ Wk, const float* __restrict__ Wq,
                        const float* __restrict__ encIn) {
    __shared__ float t[32][33];
    int z = blockIdx.z;
    if (z == 2 && blockIdx.y >= 8) return;
    const float* in = (z == 0) ? Wk : (z == 1) ? Wq : encIn;
    float* outp = (z == 0) ? g_WkT : (z == 1) ? g_WqT : g_encT;
    int in_cols = (z == 2) ? SS : HH;
    int out_cols = (z == 2) ? BB : HH;
    int x = blockIdx.x * 32 + threadIdx.x;
    int y0 = blockIdx.y * 32;
    for (int j = threadIdx.y; j < 32; j += 8) t[j][threadIdx.x] = in[(y0 + j) * in_cols + x];
    __syncthreads();
    int x2 = y0 + threadIdx.x;
    int y20 = blockIdx.x * 32;
    for (int j = threadIdx.y; j < 32; j += 8) outp[(y20 + j) * out_cols + x2] = t[threadIdx.x][j];
}

__global__ __launch_bounds__(256) void k_prep3(const float* __restrict__ bq) {
    __shared__ float As[32][33];
    __shared__ float Bs[32][33];
    int tid = threadIdx.x;
    int m0 = blockIdx.y * 32, n0 = blockIdx.x * 32;
    int lr = tid >> 3, lk = (tid & 7) << 2;
    int ty = tid >> 4, tx = tid & 15;
    float acc00 = 0.f, acc01 = 0.f, acc10 = 0.f, acc11 = 0.f;
    for (int kk = 0; kk < HH; kk += 32) {
        float4 a = *(const float4*)(g_WkT + (m0 + lr) * HH + kk + lk);
        float4 b = *(const float4*)(g_WqT + (n0 + lr) * HH + kk + lk);
        __syncthreads();
        As[lk + 0][lr] = a.x; As[lk + 1][lr] = a.y; As[lk + 2][lr] = a.z; As[lk + 3][lr] = a.w;
        Bs[lk + 0][lr] = b.x; Bs[lk + 1][lr] = b.y; Bs[lk + 2][lr] = b.z; Bs[lk + 3][lr] = b.w;
        __syncthreads();
#pragma unroll
        for (int k = 0; k < 32; ++k) {
            float a0 = As[k][ty * 2], a1 = As[k][ty * 2 + 1];
            float b0 = Bs[k][tx * 2], b1 = Bs[k][tx * 2 + 1];
            acc00 += a0 * b0; acc01 += a0 * b1;
            acc10 += a1 * b0; acc11 += a1 * b1;
        }
    }
    auto wr = [&](int m, int p, float v) {
        size_t d = (size_t)(GG + m) * HH + p;
        __nv_bfloat16 hi = __float2bfloat16(v);
        g_WA_hi[d] = hi;
        g_WA_lo[d] = __float2bfloat16(v - __bfloat162float(hi));
    };
    wr(m0 + ty * 2 + 0, n0 + tx * 2 + 0, acc00);
    wr(m0 + ty * 2 + 0, n0 + tx * 2 + 1, acc01);
    wr(m0 + ty * 2 + 1, n0 + tx * 2 + 0, acc10);
    wr(m0 + ty * 2 + 1, n0 + tx * 2 + 1, acc11);

    if (blockIdx.x == 0) {
        int wv = tid >> 5, ln = tid & 31;
#pragma unroll
        for (int it = 0; it < 4; ++it) {
            int m = m0 + wv + it * 8;
            const float* row = g_WkT + (size_t)m * HH;
            float a = 0.f;
            for (int n = ln; n < HH; n += 32) a += bq[n] * row[n];
#pragma unroll
            for (int off = 16; off; off >>= 1) a += __shfl_xor_sync(0xffffffffu, a, off);
            if (ln == 0) g_bqk[m] = a;
        }
    }
}

// ---------------- host launcher ----------------
extern "C" void kernel_launch(void* const* d_in, const int* in_sizes, int n_in,
                              void* d_out, int out_size) {
    int off = (n_in >= 18 && in_sizes[1] == 1) ? 1 : 0;
    const float* enc_inputs = (const float*)d_in[0];
    const float* embed_W = (const float*)d_in[1 + off];
    const float* embed_b = (const float*)d_in[2 + off];
    const float* enc_Wih = (const float*)d_in[3 + off];
    const float* enc_Whh = (const float*)d_in[4 + off];
    const float* enc_bih = (const float*)d_in[5 + off];
    const float* enc_bhh = (const float*)d_in[6 + off];
    const float* dec_Wih = (const float*)d_in[7 + off];
    const float* dec_Whh = (const float*)d_in[8 + off];
    const float* dec_bih = (const float*)d_in[9 + off];
    const float* dec_bhh = (const float*)d_in[10 + off];
    const float* Wq = (const float*)d_in[11 + off];
    const float* bq = (const float*)d_in[12 + off];
    const float* Wk = (const float*)d_in[13 + off];
    // bk dropped: uniform over s -> softmax-invariant
    const float* out_W = (const float*)d_in[15 + off];
    const float* out_b = (const float*)d_in[16 + off];
    float* out = (float*)d_out;

    cudaFuncSetAttribute(lstm_enc_persist, cudaFuncAttributeMaxDynamicSharedMemorySize, PSMEM);
    cudaFuncSetAttribute(dec_persist, cudaFuncAttributeMaxDynamicSharedMemorySize, SMEM_DEC);

    // ---- prep: exactly 3 launches ----
    k_prep1<<<(GG * HH) / 256, 256>>>(embed_W, embed_b, enc_Wih, enc_bih, enc_bhh,
                                      enc_Whh, dec_Wih, dec_Whh, dec_bih, dec_bhh);
    dim3 tb(32, 8);
    k_prep2<<<dim3(16, 16, 3), tb>>>(Wk, Wq, enc_inputs);
    k_prep3<<<dim3(16, 16), 256>>>(bq);

    // ---- encoder: ONE persistent kernel ----
    lstm_enc_persist<<<dim3(32, 4), 512, PSMEM>>>();

    // ---- decoder: ONE persistent kernel ----
    dec_persist<<<128, 512, SMEM_DEC>>>(out_W, out_b, out);

    (void)in_sizes; (void)n_in; (void)out_size;
}

// round 16
// speedup vs baseline: 1.2849x; 1.0006x over previous
#include <cuda_runtime.h>
#include <cuda_bf16.h>
#include <math.h>
#include <stdint.h>

#define BB 256
#define SS 512
#define RR 128
#define HH 512
#define TT 96
#define GG 2048   // 4*H
#define K2 1024   // 2*H

// ---------------- device scratch ----------------
__device__ __nv_bfloat16 g_hsb[(size_t)SS * BB * HH];   // encoder hidden states bf16 [s][b][h]
__device__ float g_hbuf[2][BB * HH];                    // ping-pong hidden fp32 (for out proj)
__device__ float g_c[BB * HH];                          // cell state fp32 (decoder)
__device__ __nv_bfloat16 g_hhi[2][BB * HH];             // bf16 h ping-pong (hi only)
__device__ __nv_bfloat16 g_ctxhi[BB * HH];              // bf16 context (hi only)
__device__ __nv_bfloat16 g_Wenc_hi[GG * HH],  g_Wenc_lo[GG * HH];
__device__ __nv_bfloat16 g_WA_hi[(GG + HH) * HH], g_WA_lo[(GG + HH) * HH]; // [gates_h | At]
__device__ __nv_bfloat16 g_Wc_hi[GG * HH], g_Wc_lo[GG * HH];               // ctx half of dec Wih
__device__ float g_gates[BB * GG];                     // cached gates_h (fp32)
__device__ float g_q2p[4][BB * HH];                    // q2 split-K partials (4-way)
__device__ float g_v2[GG], g_u2[GG], g_bd2[GG];
__device__ float g_WkT[HH * HH], g_WqT[HH * HH];
__device__ float g_bqk[HH];
__device__ float g_encT[SS * BB];                      // enc_inputs transposed [s][b]

// ---- encoder per-m-group barriers (4 groups x 32 CTAs) ----
__device__ unsigned g_mbar_count[4] = {0, 0, 0, 0};
__device__ volatile unsigned g_mbar_gen[4] = {0, 0, 0, 0};

// ---- decoder 2-level tree barrier (8 groups x 16 CTAs -> root of 8) ----
__device__ unsigned g_gcount[8] = {0, 0, 0, 0, 0, 0, 0, 0};
__device__ unsigned g_rcount = 0;
__device__ volatile unsigned g_ggen = 0;

// ---------------- helpers ----------------
__device__ __forceinline__ uint32_t smem_u32(const void* p) {
    uint32_t a;
    asm("{ .reg .u64 t; cvta.to.shared.u64 t, %1; cvt.u32.u64 %0, t; }" : "=r"(a) : "l"(p));
    return a;
}
__device__ __forceinline__ void cp16(uint32_t dst, const void* src) {
    asm volatile("cp.async.cg.shared.global [%0], [%1], 16;" :: "r"(dst), "l"(src) : "memory");
}
#define CP_COMMIT() asm volatile("cp.async.commit_group;" ::: "memory")
#define CP_WAIT2()  asm volatile("cp.async.wait_group 2;" ::: "memory")
#define CP_WAIT0()  asm volatile("cp.async.wait_group 0;" ::: "memory")

__device__ __forceinline__ void ldm4(uint32_t* r, uint32_t addr) {
    asm volatile("ldmatrix.sync.aligned.m8n8.x4.shared.b16 {%0,%1,%2,%3}, [%4];"
                 : "=r"(r[0]), "=r"(r[1]), "=r"(r[2]), "=r"(r[3]) : "r"(addr));
}
__device__ __forceinline__ void mma16816(float* c, const uint32_t* a, uint32_t b0, uint32_t b1) {
    asm volatile(
        "mma.sync.aligned.m16n8k16.row.col.f32.bf16.bf16.f32 "
        "{%0,%1,%2,%3}, {%4,%5,%6,%7}, {%8,%9}, {%0,%1,%2,%3};"
        : "+f"(c[0]), "+f"(c[1]), "+f"(c[2]), "+f"(c[3])
        : "r"(a[0]), "r"(a[1]), "r"(a[2]), "r"(a[3]), "r"(b0), "r"(b1));
}

// fast sigmoid/tanh (~2ulp via __expf)
__device__ __forceinline__ float fsig(float x) {
    return __fdividef(1.f, 1.f + __expf(-x));
}
__device__ __forceinline__ float ftanh(float x) {
    float e = __expf(2.f * x);
    return 1.f - __fdividef(2.f, e + 1.f);
}

// encoder: per-m-group barrier (32 CTAs sharing blockIdx.y)
__device__ __forceinline__ void msync(int grp) {
    __syncthreads();
    if (threadIdx.x == 0) {
        __threadfence();
        unsigned gen = g_mbar_gen[grp];
        unsigned t = atomicInc(&g_mbar_count[grp], 31);
        if (t == 31) {
            g_mbar_gen[grp] = gen + 1;
        } else {
            while (g_mbar_gen[grp] == gen) { }
        }
        __threadfence();
    }
    __syncthreads();
}

// decoder: 2-level tree barrier across 128 CTAs
__device__ __forceinline__ void grid_sync2(int cta) {
    __syncthreads();
    if (threadIdx.x == 0) {
        __threadfence();
        unsigned gen = g_ggen;
        unsigned t = atomicInc(&g_gcount[cta >> 4], 15);
        if (t == 15) {
            unsigned r = atomicInc(&g_rcount, 7);
            if (r == 7) {
                g_ggen = gen + 1;
            } else {
                while (g_ggen == gen) { }
            }
        } else {
            while (g_ggen == gen) { }
        }
        __threadfence();
    }
    __syncthreads();
}

// ---- decoder tile geometry (64-k chunks, unchanged from R15) ----
#define T_ROW   144
#define T_SZ    (64 * T_ROW)          // 9216
#define ST3     (3 * T_SZ)            // decoder stage stride (ahi, bhi, blo) 27648
#define SMEM_DEC (4 * ST3)            // 110592 (4 stages)

// ---- encoder tile geometry (NEW: 128-k chunks) ----
#define T2_ROW  272                   // 128 bf16 + 16B pad (17 units; 17%8=1 -> conflict-free)
#define T2_SZ   (64 * T2_ROW)         // 17408
#define W2_TILE (4 * T2_SZ)           // 69632 per hi; lo at +W2_TILE
#define A2_OFF  (2 * W2_TILE)         // 139264; 4 A stages x T2_SZ
#define VU_OFF  (A2_OFF + 4 * T2_SZ)  // 208896
#define PSMEM   (VU_OFF + 2048)       // 210944

// attention phase smem blocking
#define ATT_SUB 16640                 // sc 16384 + sm 32 + sl 32 (padded)

// ================= 16-warp 64x64 chunk MMA (64-k, decoder): D += Ah*(Bh+Bl) =================
__device__ __forceinline__ void chunk_mma_16w(uint32_t abase,
                                              uint32_t bbase, uint32_t blo_off,
                                              int mrow, int ncol, uint32_t rowsel,
                                              float acc[2][4]) {
#pragma unroll
    for (int kk = 0; kk < 4; ++kk) {
        uint32_t kof = kk * 32;
        uint32_t aaddr = abase + mrow * T_ROW + rowsel + kof;
        uint32_t baddr = bbase + ncol * T_ROW + rowsel + kof;
        uint32_t ahr[4], bh[4], bl2[4];
        ldm4(ahr, aaddr);
        ldm4(bh, baddr);
        ldm4(bl2, baddr + blo_off);
#pragma unroll
        for (int nt = 0; nt < 2; ++nt) {
            mma16816(acc[nt], ahr, bh[nt], bh[nt + 2]);
            mma16816(acc[nt], ahr, bl2[nt], bl2[nt + 2]);
        }
    }
}

// ================= 16-warp 64x128 chunk MMA (128-k, encoder) =================
__device__ __forceinline__ void chunk_mma_16w_k128(uint32_t abase,
                                                   uint32_t bbase, uint32_t blo_off,
                                                   int mrow, int ncol, uint32_t rowsel2,
                                                   float acc[2][4]) {
#pragma unroll
    for (int kk = 0; kk < 8; ++kk) {
        uint32_t kof = kk * 32;
        uint32_t aaddr = abase + mrow * T2_ROW + rowsel2 + kof;
        uint32_t baddr = bbase + ncol * T2_ROW + rowsel2 + kof;
        uint32_t ahr[4], bh[4], bl2[4];
        ldm4(ahr, aaddr);
        ldm4(bh, baddr);
        ldm4(bl2, baddr + blo_off);
#pragma unroll
        for (int nt = 0; nt < 2; ++nt) {
            mma16816(acc[nt], ahr, bh[nt], bh[nt + 2]);
            mma16816(acc[nt], ahr, bl2[nt], bl2[nt + 2]);
        }
    }
}

// ================= 4-stage pipelined 64x64 GEMM (decoder; row stride = HH) =================
__device__ __forceinline__ void gemm_pipe(const __nv_bfloat16* __restrict__ ahi,
                                          const __nv_bfloat16* __restrict__ bhi,
                                          const __nv_bfloat16* __restrict__ blo,
                                          int kbase, int nch, uint32_t sb, int tid,
                                          int mrow, int ncol, uint32_t rowsel,
                                          float acc[2][4]) {
    int r = tid >> 3, cu = tid & 7;
    auto issue = [&](int ch) {
        if (ch < nch) {
            size_t c0 = (size_t)kbase + ch * 64 + cu * 8;
            uint32_t d = sb + (ch & 3) * ST3 + r * T_ROW + cu * 16;
            size_t ro = (size_t)r * HH + c0;
            cp16(d,            ahi + ro);
            cp16(d +     T_SZ, bhi + ro);
            cp16(d + 2 * T_SZ, blo + ro);
        }
        CP_COMMIT();
    };
    issue(0); issue(1); issue(2);
    for (int ch = 0; ch < nch; ++ch) {
        CP_WAIT2();
        __syncthreads();
        issue(ch + 3);
        uint32_t base = sb + (ch & 3) * ST3;
        chunk_mma_16w(base, base + T_SZ, T_SZ, mrow, ncol, rowsel, acc);
    }
}

// ================= persistent encoder: 128-k chunks (4 per step) =================
__global__ __launch_bounds__(512) void lstm_enc_persist() {
    extern __shared__ char smem[];
    uint32_t sb = smem_u32(smem);
    int tid = threadIdx.x;
    int w = tid >> 5, l = tid & 31;
    int n0 = blockIdx.x * 64;
    int m0 = blockIdx.y * 64;
    int mgrp = blockIdx.y;
    int mrow = (w & 3) * 16;
    int ncol = (w >> 2) * 16;

    // weight slice (hi+lo), 4 chunks of 64 rows x 128 k -> SMEM once
    for (int i = tid; i < 4096; i += 512) {
        int c = i >> 10;                 // chunk 0..3 (1024 16B-units each)
        int r = (i >> 4) & 63, cu = i & 15;
        uint32_t d = sb + c * T2_SZ + r * T2_ROW + cu * 16;
        size_t src = (size_t)(n0 + r) * HH + c * 128 + cu * 8;
        cp16(d, g_Wenc_hi + src);
        cp16(d + W2_TILE, g_Wenc_lo + src);
    }
    CP_COMMIT();
    float* sv = (float*)(smem + VU_OFF);
    float* su = sv + 256;
    if (tid < 256) { sv[tid] = g_v2[n0 + tid]; su[tid] = g_u2[n0 + tid]; }
    CP_WAIT0();
    __syncthreads();

    int bnew = tid >> 3;
    int kp = tid & 7;
    int b = m0 + bnew;
    int hl0 = kp * 2;
    int hbase = n0 >> 2;
    float creg[2] = {0.f, 0.f};
    uint32_t rowsel2 = (l & 15) * T2_ROW + (l >> 4) * 16;

    for (int s = 0; s < SS; ++s) {
        int par = s & 1, op = par ^ 1;
        const __nv_bfloat16* __restrict__ ah = g_hhi[par];

        float acc[2][4];
#pragma unroll
        for (int nt = 0; nt < 2; ++nt)
#pragma unroll
            for (int r = 0; r < 4; ++r) acc[nt][r] = 0.f;

        // A issue: 1024 16B-units per 128-k chunk, 2 per thread
        auto issueA = [&](int c) {
            if (c < 4) {
#pragma unroll
                for (int j = 0; j < 2; ++j) {
                    int u = tid + j * 512;
                    int r = u >> 4, cu = u & 15;
                    uint32_t d = sb + A2_OFF + (c & 3) * T2_SZ + r * T2_ROW + cu * 16;
                    cp16(d, ah + (size_t)(m0 + r) * HH + c * 128 + cu * 8);
                }
            }
            CP_COMMIT();
        };

        issueA(0); issueA(1); issueA(2);
        float e = g_encT[s * BB + b];
        for (int c = 0; c < 4; ++c) {
            CP_WAIT2();
            __syncthreads();
            issueA(c + 3);
            uint32_t abase = sb + A2_OFF + (c & 3) * T2_SZ;
            uint32_t wbase = sb + c * T2_SZ;
            chunk_mma_16w_k128(abase, wbase, W2_TILE, mrow, ncol, rowsel2, acc);
        }

        // stage accums in A stage 0 region (trailing chunk-3 reads hit stage 3 only)
        float* Cs = (float*)(smem + A2_OFF);
        {
            int g = l >> 2, cc = l & 3;
#pragma unroll
            for (int nt = 0; nt < 2; ++nt) {
                int col = ncol + nt * 8 + cc * 2;
                int r0 = mrow + g, r1 = mrow + g + 8;
                Cs[r0 * 68 + col]     = acc[nt][0];
                Cs[r0 * 68 + col + 1] = acc[nt][1];
                Cs[r1 * 68 + col]     = acc[nt][2];
                Cs[r1 * 68 + col + 1] = acc[nt][3];
            }
        }
        __syncthreads();

        float4 c0 = *(float4*)&Cs[bnew * 68 + kp * 8];
        float4 c1 = *(float4*)&Cs[bnew * 68 + kp * 8 + 4];
        float4 v0 = *(float4*)&sv[kp * 8], v1 = *(float4*)&sv[kp * 8 + 4];
        float4 u0 = *(float4*)&su[kp * 8], u1 = *(float4*)&su[kp * 8 + 4];

        float h0, h1;
        {
            float ig = fsig(c0.x + e * v0.x + u0.x);
            float fg = fsig(c0.y + e * v0.y + u0.y);
            float gg = ftanh(c0.z + e * v0.z + u0.z);
            float og = fsig(c0.w + e * v0.w + u0.w);
            float cn = fg * creg[0] + ig * gg;
            h0 = og * ftanh(cn);
            creg[0] = cn;
        }
        {
            float ig = fsig(c1.x + e * v1.x + u1.x);
            float fg = fsig(c1.y + e * v1.y + u1.y);
            float gg = ftanh(c1.z + e * v1.z + u1.z);
            float og = fsig(c1.w + e * v1.w + u1.w);
            float cn = fg * creg[1] + ig * gg;
            h1 = og * ftanh(cn);
            creg[1] = cn;
        }
        int idx = b * HH + hbase + hl0;
        __nv_bfloat162 hi2;
        hi2.x = __float2bfloat16(h0);
        hi2.y = __float2bfloat16(h1);
        *(__nv_bfloat162*)&g_hhi[op][idx] = hi2;
        *(__nv_bfloat162*)&g_hsb[((size_t)s * BB + b) * HH + hbase + hl0] = hi2;
        if (s == SS - 1) {
            *(float2*)&g_c[idx] = make_float2(creg[0], creg[1]);
            *(float2*)&g_hbuf[op][idx] = make_float2(h0, h1);
        }
        msync(mgrp);
    }
}

// ================= persistent decoder: 96 steps (byte-identical to R15) =================
__global__ __launch_bounds__(512) void dec_persist(const float* __restrict__ outW,
                                                   const float* __restrict__ outb,
                                                   float* __restrict__ out) {
    extern __shared__ char smem[];
    uint32_t sb = smem_u32(smem);
    int tid = threadIdx.x, cta = blockIdx.x;
    int w = tid >> 5, l = tid & 31;
    int mrow = (w & 3) * 16, ncol = (w >> 2) * 16;
    uint32_t rowsel = (l & 15) * T_ROW + (l >> 4) * 16;
    int g2 = l >> 2, cc = l & 3;

    for (int t = 0; t < TT; ++t) {
        int par = t & 1, op = par ^ 1;
        const __nv_bfloat16* __restrict__ ah = g_hhi[par];

        // ---------- Phase A round 1: gates_h (128 tiles, 1/CTA) ----------
        {
            int n0 = (cta & 31) * 64;
            int m0 = (cta >> 5) * 64;
            float acc[2][4];
#pragma unroll
            for (int nt = 0; nt < 2; ++nt)
#pragma unroll
                for (int r = 0; r < 4; ++r) acc[nt][r] = 0.f;
            gemm_pipe(ah + (size_t)m0 * HH,
                      g_WA_hi + (size_t)n0 * HH, g_WA_lo + (size_t)n0 * HH,
                      0, 8, sb, tid, mrow, ncol, rowsel, acc);
#pragma unroll
            for (int nt = 0; nt < 2; ++nt) {
                int col = n0 + ncol + nt * 8 + cc * 2;
                int r0 = m0 + mrow + g2, r1 = r0 + 8;
                *(float2*)(g_gates + r0 * GG + col) = make_float2(acc[nt][0], acc[nt][1]);
                *(float2*)(g_gates + r1 * GG + col) = make_float2(acc[nt][2], acc[nt][3]);
            }
        }

        // ---------- Phase A round 2: q2 partials, 4-way split-K ----------
        {
            int quarter = cta & 3;
            int idx = cta >> 2;            // 0..31
            int nq0 = (idx & 7) * 64;
            int m0 = (idx >> 3) * 64;
            float acc[2][4];
#pragma unroll
            for (int nt = 0; nt < 2; ++nt)
#pragma unroll
                for (int r = 0; r < 4; ++r) acc[nt][r] = 0.f;
            gemm_pipe(ah + (size_t)m0 * HH,
                      g_WA_hi + (size_t)(GG + nq0) * HH, g_WA_lo + (size_t)(GG + nq0) * HH,
                      quarter * 128, 2, sb, tid, mrow, ncol, rowsel, acc);
#pragma unroll
            for (int nt = 0; nt < 2; ++nt) {
                int q = nq0 + ncol + nt * 8 + cc * 2;
                int r0 = m0 + mrow + g2, r1 = r0 + 8;
                float b0 = (quarter == 0) ? g_bqk[q] : 0.f;
                float b1 = (quarter == 0) ? g_bqk[q + 1] : 0.f;
                *(float2*)(g_q2p[quarter] + r0 * HH + q) = make_float2(acc[nt][0] + b0, acc[nt][1] + b1);
                *(float2*)(g_q2p[quarter] + r1 * HH + q) = make_float2(acc[nt][2] + b0, acc[nt][3] + b1);
            }
        }
        grid_sync2(cta);

        // ---------- Phase B: attention, 2 batches per CTA, depth-2 prefetch ----------
        {
            int sub = tid >> 8, stid = tid & 255;
            int sw = stid >> 5, ln = stid & 31;
            int b = cta * 2 + sub;

            float qf[16];
            {
#pragma unroll
                for (int i = 0; i < 4; ++i) {
                    float4 va = *(const float4*)(g_q2p[0] + b * HH + ln * 16 + i * 4);
                    float4 vb = *(const float4*)(g_q2p[1] + b * HH + ln * 16 + i * 4);
                    float4 vc = *(const float4*)(g_q2p[2] + b * HH + ln * 16 + i * 4);
                    float4 vd = *(const float4*)(g_q2p[3] + b * HH + ln * 16 + i * 4);
                    qf[i * 4 + 0] = va.x + vb.x + vc.x + vd.x;
                    qf[i * 4 + 1] = va.y + vb.y + vc.y + vd.y;
                    qf[i * 4 + 2] = va.z + vb.z + vc.z + vd.z;
                    qf[i * 4 + 3] = va.w + vb.w + vc.w + vd.w;
                }
            }

            float m = -INFINITY, lsum = 0.f;
            float ca[16];
#pragma unroll
            for (int q = 0; q < 16; ++q) ca[q] = 0.f;

            const __nv_bfloat16* base = g_hsb + (size_t)b * HH + (size_t)ln * 16;
            uint4 p0[2], p1[2];
            {
                const __nv_bfloat16* hb = base + (size_t)(sw + 0 * 8) * BB * HH;
                p0[0] = *(const uint4*)hb; p1[0] = *(const uint4*)(hb + 8);
                hb = base + (size_t)(sw + 1 * 8) * BB * HH;
                p0[1] = *(const uint4*)hb; p1[1] = *(const uint4*)(hb + 8);
            }

#pragma unroll 4
            for (int it = 0; it < SS / 8; ++it) {
                int slot = it & 1;
                uint4 c0 = p0[slot], c1 = p1[slot];
                if (it + 2 < SS / 8) {
                    const __nv_bfloat16* hb = base + (size_t)(sw + (it + 2) * 8) * BB * HH;
                    p0[slot] = *(const uint4*)hb;
                    p1[slot] = *(const uint4*)(hb + 8);
                }
                float f[16];
                {
                    const __nv_bfloat162* q0 = (const __nv_bfloat162*)&c0;
                    const __nv_bfloat162* q1 = (const __nv_bfloat162*)&c1;
#pragma unroll
                    for (int j = 0; j < 4; ++j) {
                        float2 v = __bfloat1622float2(q0[j]);
                        f[2 * j] = v.x; f[2 * j + 1] = v.y;
                        float2 v2 = __bfloat1622float2(q1[j]);
                        f[8 + 2 * j] = v2.x; f[8 + 2 * j + 1] = v2.y;
                    }
                }
                float dot = 0.f;
#pragma unroll
                for (int q = 0; q < 16; ++q) dot += f[q] * qf[q];
#pragma unroll
                for (int off = 16; off; off >>= 1) dot += __shfl_xor_sync(0xffffffffu, dot, off);
                float mn = fmaxf(m, dot);
                float scl = __expf(m - mn);
                float p = __expf(dot - mn);
                m = mn;
                lsum = lsum * scl + p;
#pragma unroll
                for (int q = 0; q < 16; ++q) ca[q] = ca[q] * scl + p * f[q];
            }

            float* sc = (float*)(smem + sub * ATT_SUB);
            float* smx = (float*)(smem + sub * ATT_SUB + 16384);
            float* slx = (float*)(smem + sub * ATT_SUB + 16416);
#pragma unroll
            for (int q = 0; q < 16; ++q) sc[sw * HH + ln * 16 + q] = ca[q];
            if (ln == 0) { smx[sw] = m; slx[sw] = lsum; }
            __syncthreads();

            float M = smx[0];
#pragma unroll
            for (int w2 = 1; w2 < 8; ++w2) M = fmaxf(M, smx[w2]);
            float ew[8];
            float L = 0.f;
#pragma unroll
            for (int w2 = 0; w2 < 8; ++w2) { ew[w2] = __expf(smx[w2] - M); L += slx[w2] * ew[w2]; }
            float invL = __fdividef(1.f, L);
            {
                int h = stid * 2;
                float va = 0.f, vb = 0.f;
#pragma unroll
                for (int w2 = 0; w2 < 8; ++w2) {
                    va += ew[w2] * sc[w2 * HH + h];
                    vb += ew[w2] * sc[w2 * HH + h + 1];
                }
                va *= invL; vb *= invL;
                __nv_bfloat162 hi2;
                hi2.x = __float2bfloat16(va);
                hi2.y = __float2bfloat16(vb);
                *(__nv_bfloat162*)&g_ctxhi[b * HH + h] = hi2;
            }
        }
        grid_sync2(cta);

        // ---------- Phase C: gates += ctx @ Wc^T, LSTM epilogue ----------
        {
            int n0 = (cta & 31) * 64;
            int m0 = (cta >> 5) * 64;
            float acc[2][4];
#pragma unroll
            for (int nt = 0; nt < 2; ++nt)
#pragma unroll
                for (int r = 0; r < 4; ++r) acc[nt][r] = 0.f;
            gemm_pipe(g_ctxhi + (size_t)m0 * HH,
                      g_Wc_hi + (size_t)n0 * HH, g_Wc_lo + (size_t)n0 * HH,
                      0, 8, sb, tid, mrow, ncol, rowsel, acc);

            float* Cs = (float*)smem;
            {
#pragma unroll
                for (int nt = 0; nt < 2; ++nt) {
                    int col = ncol + nt * 8 + cc * 2;
                    int r0 = mrow + g2, r1 = mrow + g2 + 8;
                    Cs[r0 * 68 + col]     = acc[nt][0];
                    Cs[r0 * 68 + col + 1] = acc[nt][1];
                    Cs[r1 * 68 + col]     = acc[nt][2];
                    Cs[r1 * 68 + col + 1] = acc[nt][3];
                }
            }
            __syncthreads();

            int bnew = tid >> 3, kp = tid & 7;
            int b = m0 + bnew;
            int hl0 = kp * 2;
            int hbase = n0 >> 2;
            int jp = n0 + kp * 8;
            float4 c0 = *(float4*)&Cs[bnew * 68 + kp * 8];
            float4 c1 = *(float4*)&Cs[bnew * 68 + kp * 8 + 4];
            float4 gr0 = *(const float4*)(g_gates + (size_t)b * GG + jp);
            float4 gr1 = *(const float4*)(g_gates + (size_t)b * GG + jp + 4);
            float4 bd0 = *(const float4*)(g_bd2 + jp);
            float4 bd1 = *(const float4*)(g_bd2 + jp + 4);
            int idx = b * HH + hbase + hl0;
            float2 cold = *(float2*)&g_c[idx];
            float h0, h1, cn0, cn1;
            {
                float ig = fsig(c0.x + gr0.x + bd0.x);
                float fg = fsig(c0.y + gr0.y + bd0.y);
                float gg = ftanh(c0.z + gr0.z + bd0.z);
                float og = fsig(c0.w + gr0.w + bd0.w);
                cn0 = fg * cold.x + ig * gg;
                h0 = og * ftanh(cn0);
            }
            {
                float ig = fsig(c1.x + gr1.x + bd1.x);
                float fg = fsig(c1.y + gr1.y + bd1.y);
                float gg = ftanh(c1.z + gr1.z + bd1.z);
                float og = fsig(c1.w + gr1.w + bd1.w);
                cn1 = fg * cold.y + ig * gg;
                h1 = og * ftanh(cn1);
            }
            *(float2*)&g_c[idx] = make_float2(cn0, cn1);
            *(float2*)&g_hbuf[op][idx] = make_float2(h0, h1);
            __nv_bfloat162 hi2;
            hi2.x = __float2bfloat16(h0);
            hi2.y = __float2bfloat16(h1);
            *(__nv_bfloat162*)&g_hhi[op][idx] = hi2;
        }
        grid_sync2(cta);

        // ---------- Phase D: output projection ----------
        if (w < 2) {
            int b = cta * 2 + w;
            const float* hp = g_hbuf[op] + b * HH;
            float p = 0.f;
#pragma unroll
            for (int q = 0; q < 16; ++q) p += hp[l + (q << 5)] * outW[l + (q << 5)];
#pragma unroll
            for (int off = 16; off; off >>= 1) p += __shfl_xor_sync(0xffffffffu, p, off);
            if (l == 0) out[b * TT + t] = p + outb[0];
        }
    }
}

// ================= prep (3 launches total) =================
__global__ void k_prep1(const float* __restrict__ embW, const float* __restrict__ embb,
                        const float* __restrict__ encWih, const float* __restrict__ encbih,
                        const float* __restrict__ encbhh, const float* __restrict__ encWhh,
                        const float* __restrict__ dWih, const float* __restrict__ dWhh,
                        const float* __restrict__ dbih, const float* __restrict__ dbhh) {
    int idx = blockIdx.x * 256 + threadIdx.x;
    {
        int jp = idx >> 9, k = idx & (HH - 1);
        int h = jp >> 2, g = jp & 3;
        float we = encWhh[(g * HH + h) * HH + k];
        __nv_bfloat16 hie = __float2bfloat16(we);
        g_Wenc_hi[idx] = hie;
        g_Wenc_lo[idx] = __float2bfloat16(we - __bfloat162float(hie));
        float wa = dWih[(g * HH + h) * K2 + k] + dWhh[(g * HH + h) * HH + k];
        __nv_bfloat16 hia = __float2bfloat16(wa);
        g_WA_hi[idx] = hia;
        g_WA_lo[idx] = __float2bfloat16(wa - __bfloat162float(hia));
        float wc = dWih[(g * HH + h) * K2 + HH + k];
        __nv_bfloat16 hic = __float2bfloat16(wc);
        g_Wc_hi[idx] = hic;
        g_Wc_lo[idx] = __float2bfloat16(wc - __bfloat162float(hic));
    }
    if (idx < GG) {
        int h = idx >> 2, g = idx & 3;
        int j = g * HH + h;
        float v = 0.f, u = 0.f;
        const float* wr = encWih + j * RR;
#pragma unroll 8
        for (int r = 0; r < RR; ++r) { v += embW[r] * wr[r]; u += embb[r] * wr[r]; }
        g_v2[idx] = v;
        g_u2[idx] = u + encbih[j] + encbhh[j];
        g_bd2[idx] = dbih[j] + dbhh[j];
    }
    if (idx < BB * HH) {
        g_hhi[0][idx] = __float2bfloat16(0.f);
    }
}

// P2: transposes. z=0: Wk->WkT, z=1: Wq->WqT, z=2: enc_inputs [B,S]->g_encT [S,B]
__global__ void k_prep2(const float* __restrict__ Wk, const float* __restrict__ Wq,
                        const float* __restrict__ encIn) {
    __shared__ float t[32][33];
    int z = blockIdx.z;
    if (z == 2 && blockIdx.y >= 8) return;
    const float* in = (z == 0) ? Wk : (z == 1) ? Wq : encIn;
    float* outp = (z == 0) ? g_WkT : (z == 1) ? g_WqT : g_encT;
    int in_cols = (z == 2) ? SS : HH;
    int out_cols = (z == 2) ? BB : HH;
    int x = blockIdx.x * 32 + threadIdx.x;
    int y0 = blockIdx.y * 32;
    for (int j = threadIdx.y; j < 32; j += 8) t[j][threadIdx.x] = in[(y0 + j) * in_cols + x];
    __syncthreads();
    int x2 = y0 + threadIdx.x;
    int y20 = blockIdx.x * 32;
    for (int j = threadIdx.y; j < 32; j += 8) outp[(y20 + j) * out_cols + x2] = t[threadIdx.x][j];
}

__global__ __launch_bounds__(256) void k_prep3(const float* __restrict__ bq) {
    __shared__ float As[32][33];
    __shared__ float Bs[32][33];
    int tid = threadIdx.x;
    int m0 = blockIdx.y * 32, n0 = blockIdx.x * 32;
    int lr = tid >> 3, lk = (tid & 7) << 2;
    int ty = tid >> 4, tx = tid & 15;
    float acc00 = 0.f, acc01 = 0.f, acc10 = 0.f, acc11 = 0.f;
    for (int kk = 0; kk < HH; kk += 32) {
        float4 a = *(const float4*)(g_WkT + (m0 + lr) * HH + kk + lk);
        float4 b = *(const float4*)(g_WqT + (n0 + lr) * HH + kk + lk);
        __syncthreads();
        As[lk + 0][lr] = a.x; As[lk + 1][lr] = a.y; As[lk + 2][lr] = a.z; As[lk + 3][lr] = a.w;
        Bs[lk + 0][lr] = b.x; Bs[lk + 1][lr] = b.y; Bs[lk + 2][lr] = b.z; Bs[lk + 3][lr] = b.w;
        __syncthreads();
#pragma unroll
        for (int k = 0; k < 32; ++k) {
            float a0 = As[k][ty * 2], a1 = As[k][ty * 2 + 1];
            float b0 = Bs[k][tx * 2], b1 = Bs[k][tx * 2 + 1];
            acc00 += a0 * b0; acc01 += a0 * b1;
            acc10 += a1 * b0; acc11 += a1 * b1;
        }
    }
    auto wr = [&](int m, int p, float v) {
        size_t d = (size_t)(GG + m) * HH + p;
        __nv_bfloat16 hi = __float2bfloat16(v);
        g_WA_hi[d] = hi;
        g_WA_lo[d] = __float2bfloat16(v - __bfloat162float(hi));
    };
    wr(m0 + ty * 2 + 0, n0 + tx * 2 + 0, acc00);
    wr(m0 + ty * 2 + 0, n0 + tx * 2 + 1, acc01);
    wr(m0 + ty * 2 + 1, n0 + tx * 2 + 0, acc10);
    wr(m0 + ty * 2 + 1, n0 + tx * 2 + 1, acc11);

    if (blockIdx.x == 0) {
        int wv = tid >> 5, ln = tid & 31;
#pragma unroll
        for (int it = 0; it < 4; ++it) {
            int m = m0 + wv + it * 8;
            const float* row = g_WkT + (size_t)m * HH;
            float a = 0.f;
            for (int n = ln; n < HH; n += 32) a += bq[n] * row[n];
#pragma unroll
            for (int off = 16; off; off >>= 1) a += __shfl_xor_sync(0xffffffffu, a, off);
            if (ln == 0) g_bqk[m] = a;
        }
    }
}

// ---------------- host launcher ----------------
extern "C" void kernel_launch(void* const* d_in, const int* in_sizes, int n_in,
                              void* d_out, int out_size) {
    int off = (n_in >= 18 && in_sizes[1] == 1) ? 1 : 0;
    const float* enc_inputs = (const float*)d_in[0];
    const float* embed_W = (const float*)d_in[1 + off];
    const float* embed_b = (const float*)d_in[2 + off];
    const float* enc_Wih = (const float*)d_in[3 + off];
    const float* enc_Whh = (const float*)d_in[4 + off];
    const float* enc_bih = (const float*)d_in[5 + off];
    const float* enc_bhh = (const float*)d_in[6 + off];
    const float* dec_Wih = (const float*)d_in[7 + off];
    const float* dec_Whh = (const float*)d_in[8 + off];
    const float* dec_bih = (const float*)d_in[9 + off];
    const float* dec_bhh = (const float*)d_in[10 + off];
    const float* Wq = (const float*)d_in[11 + off];
    const float* bq = (const float*)d_in[12 + off];
    const float* Wk = (const float*)d_in[13 + off];
    // bk dropped: uniform over s -> softmax-invariant
    const float* out_W = (const float*)d_in[15 + off];
    const float* out_b = (const float*)d_in[16 + off];
    float* out = (float*)d_out;

    cudaFuncSetAttribute(lstm_enc_persist, cudaFuncAttributeMaxDynamicSharedMemorySize, PSMEM);
    cudaFuncSetAttribute(dec_persist, cudaFuncAttributeMaxDynamicSharedMemorySize, SMEM_DEC);

    // ---- prep: exactly 3 launches ----
    k_prep1<<<(GG * HH) / 256, 256>>>(embed_W, embed_b, enc_Wih, enc_bih, enc_bhh,
                                      enc_Whh, dec_Wih, dec_Whh, dec_bih, dec_bhh);
    dim3 tb(32, 8);
    k_prep2<<<dim3(16, 16, 3), tb>>>(Wk, Wq, enc_inputs);
    k_prep3<<<dim3(16, 16), 256>>>(bq);

    // ---- encoder: ONE persistent kernel (128-k chunks) ----
    lstm_enc_persist<<<dim3(32, 4), 512, PSMEM>>>();

    // ---- decoder: ONE persistent kernel ----
    dec_persist<<<128, 512, SMEM_DEC>>>(out_W, out_b, out);

    (void)in_sizes; (void)n_in; (void)out_size;
}